// round 2
// baseline (speedup 1.0000x reference)
#include <cuda_runtime.h>

#define Bn 1024
#define Tn 128
#define Hd 64
#define NZv 5
#define ACTD 20
#define Rr 8
#define SCAN_THREADS 256

// ---------------- device scratch (static allocation only) ----------------
__device__ float g_phix[(size_t)Tn * Bn * Hd];          // (T,B,H)
__device__ float g_eps[(size_t)(Tn + 1) * Bn * Hd];     // (T+1,B,H)
__device__ float g_kld[Bn];

// ---------------- math helpers ----------------
__device__ __forceinline__ float softplusf(float x) {
    // jax.nn.softplus = logaddexp(x, 0) = max(x,0) + log1p(exp(-|x|))
    return fmaxf(x, 0.0f) + log1pf(expf(-fabsf(x)));
}
__device__ __forceinline__ float sigmoidf(float x) {
    return 1.0f / (1.0f + expf(-x));
}

// XLA ErfInv32 (Giles) polynomial
__device__ __forceinline__ float erfinv_f(float x) {
    float w = -__logf((1.0f - x) * (1.0f + x));
    float p;
    if (w < 5.0f) {
        w = w - 2.5f;
        p = 2.81022636e-08f;
        p = fmaf(p, w, 3.43273939e-07f);
        p = fmaf(p, w, -3.5233877e-06f);
        p = fmaf(p, w, -4.39150654e-06f);
        p = fmaf(p, w, 0.00021858087f);
        p = fmaf(p, w, -0.00125372503f);
        p = fmaf(p, w, -0.00417768164f);
        p = fmaf(p, w, 0.246640727f);
        p = fmaf(p, w, 1.50140941f);
    } else {
        w = sqrtf(w) - 3.0f;
        p = -0.000200214257f;
        p = fmaf(p, w, 0.000100950558f);
        p = fmaf(p, w, 0.00134934322f);
        p = fmaf(p, w, -0.00367342844f);
        p = fmaf(p, w, 0.00573950773f);
        p = fmaf(p, w, -0.0076224613f);
        p = fmaf(p, w, 0.00943887047f);
        p = fmaf(p, w, 1.00167406f);
        p = fmaf(p, w, 2.83297682f);
    }
    return p * x;
}

// JAX threefry2x32 (20 rounds, key injection every 4)
__device__ __forceinline__ uint2 threefry2x32(unsigned k0, unsigned k1,
                                              unsigned x0, unsigned x1) {
    unsigned ks2 = k0 ^ k1 ^ 0x1BD11BDAu;
#define TF_RND(r) { x0 += x1; x1 = (x1 << (r)) | (x1 >> (32 - (r))); x1 ^= x0; }
    x0 += k0; x1 += k1;
    TF_RND(13) TF_RND(15) TF_RND(26) TF_RND(6)
    x0 += k1;  x1 += ks2 + 1u;
    TF_RND(17) TF_RND(29) TF_RND(16) TF_RND(24)
    x0 += ks2; x1 += k0 + 2u;
    TF_RND(13) TF_RND(15) TF_RND(26) TF_RND(6)
    x0 += k0;  x1 += k1 + 3u;
    TF_RND(17) TF_RND(29) TF_RND(16) TF_RND(24)
    x0 += k1;  x1 += ks2 + 4u;
    TF_RND(13) TF_RND(15) TF_RND(26) TF_RND(6)
    x0 += ks2; x1 += k0 + 5u;
#undef TF_RND
    uint2 r; r.x = x0; r.y = x1; return r;
}

// bits -> JAX uniform(-0.99999994, 1.0) -> sqrt(2)*erfinv
__device__ __forceinline__ float normal_from_bits(unsigned bits) {
    float f = __uint_as_float((bits >> 9) | 0x3F800000u) - 1.0f;  // [0,1)
    float u = fmaf(f, 2.0f, -0.99999994f);   // (maxval-minval) rounds to exactly 2.0f
    u = fmaxf(u, -0.99999994f);
    return 1.41421356f * erfinv_f(u);
}

// ---------------- kernel 1: eps precompute (129 x 1024 x 64) ----------------
// JAX threefry_partitionable=True (default in modern JAX):
//   bits[e] = y0 ^ y1  where (y0,y1) = threefry_block(key, (hi32(e), lo32(e)))
// For size 65,536,000 < 2^32 the hi counter word is always 0.
__global__ void __launch_bounds__(256) eps_kernel() {
    int gid = blockIdx.x * blockDim.x + threadIdx.x;   // exactly 129*65536 threads
    int t = gid >> 16;                 // Bn*Hd = 65536 per timestep
    unsigned bz = (unsigned)(gid & 0xFFFF);
    // folded key: threefry_block((0,42), (0,t))
    uint2 kk = threefry2x32(0u, 42u, 0u, (unsigned)t);
    float sum = 0.0f;
    unsigned e0 = bz;                  // samples s = 0,2,4,...
    unsigned e1 = bz + 65536u;         // samples s = 1,3,5,...
    #pragma unroll 1
    for (int s = 0; s < 500; s++) {    // two independent cipher chains for ILP
        uint2 oa = threefry2x32(kk.x, kk.y, 0u, e0);
        uint2 ob = threefry2x32(kk.x, kk.y, 0u, e1);
        sum += normal_from_bits(oa.x ^ oa.y);
        sum += normal_from_bits(ob.x ^ ob.y);
        e0 += 131072u;
        e1 += 131072u;
    }
    g_eps[gid] = sum * 0.001f;
}

// ---------------- kernel 2: per-(b,t) embedding -> phi_x (T,B,H) ----------------
__global__ void __launch_bounds__(64) embed_kernel(
    const int* __restrict__ acts, const float* __restrict__ durs,
    const float* __restrict__ W_act, const float* __restrict__ b_act,
    const float* __restrict__ W_dur, const float* __restrict__ b_dur,
    const float* __restrict__ W_x, const float* __restrict__ b_x)
{
    __shared__ float inp[2 * Hd];
    int rid = blockIdx.x;             // 0..B*T-1
    int b = rid / Tn, t = rid % Tn;
    int j = threadIdx.x;
    int a = acts[b * Tn + t];
    float du = durs[b * Tn + t];
    inp[j]      = fmaxf(W_act[a * Hd + j] + b_act[j], 0.0f);
    inp[Hd + j] = fmaxf(fmaf(du, W_dur[j], b_dur[j]), 0.0f);
    __syncthreads();
    float acc = b_x[j];
    #pragma unroll 16
    for (int i = 0; i < 2 * Hd; i++) acc = fmaf(inp[i], W_x[i * Hd + j], acc);
    g_phix[((size_t)t * Bn + b) * Hd + j] = fmaxf(acc, 0.0f);
}

// ---------------- kernel 3: sequential scan, parallel over batch rows ----------------
__global__ void __launch_bounds__(SCAN_THREADS) scan_kernel(
    const float* __restrict__ W_act, const float* __restrict__ b_act,
    const float* __restrict__ W_z,  const float* __restrict__ b_z,
    const float* __restrict__ Wp1,  const float* __restrict__ bp1,
    const float* __restrict__ Wp2,  const float* __restrict__ bp2,
    const float* __restrict__ Wq1,  const float* __restrict__ bq1,
    const float* __restrict__ Wq2,  const float* __restrict__ bq2,
    const float* __restrict__ W_dec,const float* __restrict__ b_dec,
    const float* __restrict__ W_a,  const float* __restrict__ b_a,
    const float* __restrict__ W_durd,const float* __restrict__ b_durd,
    const float* __restrict__ W_ih, const float* __restrict__ W_hh,
    const float* __restrict__ b_ih, const float* __restrict__ b_hh,
    const float* __restrict__ gpost,const float* __restrict__ gprior,
    float* __restrict__ out)
{
    __shared__ float sh[Rr][Hd];            // h
    __shared__ float sx[Rr][Hd];            // phi_x (reused as dec in epilogue)
    __shared__ float s_h1[Rr][NZv][Hd];     // mixture hidden (post, then prior)
    __shared__ float s_mp[Rr][Hd];          // m_post (reused as phi_logits)
    __shared__ float s_mq[Rr][Hd];          // m_prior
    __shared__ float s_z[Rr][Hd];           // z
    __shared__ float s_pz[Rr][Hd];          // phi_z
    __shared__ float s_gi[Rr][3 * Hd];      // GRU input gates (reused as logits)
    __shared__ float s_gh[Rr][3 * Hd];      // GRU hidden gates
    __shared__ float s_kld[Rr];

    const int tid = threadIdx.x;
    const int row0 = blockIdx.x * Rr;

    for (int idx = tid; idx < Rr * Hd; idx += SCAN_THREADS)
        sh[idx >> 6][idx & 63] = 0.0f;
    if (tid < Rr) s_kld[tid] = 0.0f;
    __syncthreads();

    for (int t = 0; t < Tn; t++) {
        // load phi_x for this step
        for (int idx = tid; idx < Rr * Hd; idx += SCAN_THREADS) {
            int r = idx >> 6, j = idx & 63;
            sx[r][j] = g_phix[((size_t)t * Bn + row0 + r) * Hd + j];
        }
        __syncthreads();

        // S1: posterior mixture hidden: h1 = relu([phi_x,h] @ Wp1[n] + bp1)
        for (int idx = tid; idx < Rr * NZv * Hd; idx += SCAN_THREADS) {
            int o = idx & 63, n = (idx >> 6) % NZv, r = idx / (NZv * Hd);
            const float* w = Wp1 + (size_t)n * 128 * Hd + o;
            float acc = bp1[n * Hd + o];
            #pragma unroll 8
            for (int i = 0; i < Hd; i++) acc = fmaf(sx[r][i], w[i * Hd], acc);
            #pragma unroll 8
            for (int i = 0; i < Hd; i++) acc = fmaf(sh[r][i], w[(Hd + i) * Hd], acc);
            s_h1[r][n][o] = fmaxf(acc, 0.0f);
        }
        __syncthreads();

        // S2: m_post[z] = sum_n gamma_post[n] * (h1[n] @ Wp2[n] + bp2[n])
        for (int idx = tid; idx < Rr * Hd; idx += SCAN_THREADS) {
            int zc = idx & 63, r = idx >> 6;
            float m = 0.0f;
            for (int n = 0; n < NZv; n++) {
                const float* w = Wp2 + (size_t)n * Hd * Hd + zc;
                float acc = bp2[n * Hd + zc];
                #pragma unroll 8
                for (int o = 0; o < Hd; o++) acc = fmaf(s_h1[r][n][o], w[o * Hd], acc);
                m = fmaf(gpost[n], acc, m);
            }
            s_mp[r][zc] = m;
        }
        __syncthreads();

        // S3: prior mixture hidden: h1 = relu(h @ Wq1[n] + bq1)
        for (int idx = tid; idx < Rr * NZv * Hd; idx += SCAN_THREADS) {
            int o = idx & 63, n = (idx >> 6) % NZv, r = idx / (NZv * Hd);
            const float* w = Wq1 + (size_t)n * Hd * Hd + o;
            float acc = bq1[n * Hd + o];
            #pragma unroll 8
            for (int i = 0; i < Hd; i++) acc = fmaf(sh[r][i], w[i * Hd], acc);
            s_h1[r][n][o] = fmaxf(acc, 0.0f);
        }
        __syncthreads();

        // S4: m_prior
        for (int idx = tid; idx < Rr * Hd; idx += SCAN_THREADS) {
            int zc = idx & 63, r = idx >> 6;
            float m = 0.0f;
            for (int n = 0; n < NZv; n++) {
                const float* w = Wq2 + (size_t)n * Hd * Hd + zc;
                float acc = bq2[n * Hd + zc];
                #pragma unroll 8
                for (int o = 0; o < Hd; o++) acc = fmaf(s_h1[r][n][o], w[o * Hd], acc);
                m = fmaf(gprior[n], acc, m);
            }
            s_mq[r][zc] = m;
        }
        __syncthreads();

        // S5: KL + z = pm + ps * eps
        for (int idx = tid; idx < Rr * Hd; idx += SCAN_THREADS) {
            int zc = idx & 63, r = idx >> 6;
            float mp = s_mp[r][zc], mq = s_mq[r][zc];
            float pm = fmaxf(mp, 0.0f), qm = fmaxf(mq, 0.0f);
            float ps = softplusf(mp),   qs = softplusf(mq);
            float d = pm - qm;
            float kt = logf(qs / ps) + (ps * ps + d * d) / (2.0f * qs * qs) - 0.5f;
            atomicAdd(&s_kld[r], kt);
            float e = g_eps[((size_t)t * Bn + row0 + r) * Hd + zc];
            s_z[r][zc] = fmaf(ps, e, pm);
        }
        __syncthreads();

        // S6: phi_z = relu(z @ W_z + b_z)
        for (int idx = tid; idx < Rr * Hd; idx += SCAN_THREADS) {
            int j = idx & 63, r = idx >> 6;
            float acc = b_z[j];
            #pragma unroll 8
            for (int i = 0; i < Hd; i++) acc = fmaf(s_z[r][i], W_z[i * Hd + j], acc);
            s_pz[r][j] = fmaxf(acc, 0.0f);
        }
        __syncthreads();

        // S7: GRU gates gi = [phi_x,phi_z]@W_ih + b_ih ; gh = h@W_hh + b_hh
        for (int idx = tid; idx < Rr * 3 * Hd; idx += SCAN_THREADS) {
            int k = idx % (3 * Hd), r = idx / (3 * Hd);
            const float* wih = W_ih + k;
            float a1 = b_ih[k];
            #pragma unroll 8
            for (int i = 0; i < Hd; i++) a1 = fmaf(sx[r][i],  wih[i * 3 * Hd], a1);
            #pragma unroll 8
            for (int i = 0; i < Hd; i++) a1 = fmaf(s_pz[r][i], wih[(Hd + i) * 3 * Hd], a1);
            s_gi[r][k] = a1;
            const float* whh = W_hh + k;
            float a2 = b_hh[k];
            #pragma unroll 8
            for (int i = 0; i < Hd; i++) a2 = fmaf(sh[r][i], whh[i * 3 * Hd], a2);
            s_gh[r][k] = a2;
        }
        __syncthreads();

        // S8: h update
        for (int idx = tid; idx < Rr * Hd; idx += SCAN_THREADS) {
            int j = idx & 63, r = idx >> 6;
            float ir = s_gi[r][j], iz = s_gi[r][Hd + j], in_ = s_gi[r][2 * Hd + j];
            float hr = s_gh[r][j], hz = s_gh[r][Hd + j], hn  = s_gh[r][2 * Hd + j];
            float rg = sigmoidf(ir + hr);
            float zz = sigmoidf(iz + hz);
            float nn = tanhf(fmaf(rg, hn, in_));
            sh[r][j] = (1.0f - zz) * nn + zz * sh[r][j];
        }
        __syncthreads();
    }

    // ---------- epilogue (t = Tn): prior, z, phi_z, dec, logits, dur ----------
    for (int idx = tid; idx < Rr * NZv * Hd; idx += SCAN_THREADS) {
        int o = idx & 63, n = (idx >> 6) % NZv, r = idx / (NZv * Hd);
        const float* w = Wq1 + (size_t)n * Hd * Hd + o;
        float acc = bq1[n * Hd + o];
        #pragma unroll 8
        for (int i = 0; i < Hd; i++) acc = fmaf(sh[r][i], w[i * Hd], acc);
        s_h1[r][n][o] = fmaxf(acc, 0.0f);
    }
    __syncthreads();
    for (int idx = tid; idx < Rr * Hd; idx += SCAN_THREADS) {
        int zc = idx & 63, r = idx >> 6;
        float m = 0.0f;
        for (int n = 0; n < NZv; n++) {
            const float* w = Wq2 + (size_t)n * Hd * Hd + zc;
            float acc = bq2[n * Hd + zc];
            #pragma unroll 8
            for (int o = 0; o < Hd; o++) acc = fmaf(s_h1[r][n][o], w[o * Hd], acc);
            m = fmaf(gprior[n], acc, m);
        }
        float qm = fmaxf(m, 0.0f), qs = softplusf(m);
        float e = g_eps[((size_t)Tn * Bn + row0 + r) * Hd + zc];
        s_z[r][zc] = fmaf(qs, e, qm);
    }
    __syncthreads();
    for (int idx = tid; idx < Rr * Hd; idx += SCAN_THREADS) {   // phi_z
        int j = idx & 63, r = idx >> 6;
        float acc = b_z[j];
        #pragma unroll 8
        for (int i = 0; i < Hd; i++) acc = fmaf(s_z[r][i], W_z[i * Hd + j], acc);
        s_pz[r][j] = fmaxf(acc, 0.0f);
    }
    __syncthreads();
    for (int idx = tid; idx < Rr * Hd; idx += SCAN_THREADS) {   // dec = relu([phi_z,h]@W_dec+b)
        int j = idx & 63, r = idx >> 6;
        float acc = b_dec[j];
        #pragma unroll 8
        for (int i = 0; i < Hd; i++) acc = fmaf(s_pz[r][i], W_dec[i * Hd + j], acc);
        #pragma unroll 8
        for (int i = 0; i < Hd; i++) acc = fmaf(sh[r][i],  W_dec[(Hd + i) * Hd + j], acc);
        sx[r][j] = fmaxf(acc, 0.0f);
    }
    __syncthreads();
    for (int idx = tid; idx < Rr * ACTD; idx += SCAN_THREADS) {  // logits
        int a = idx % ACTD, r = idx / ACTD;
        float acc = b_a[a];
        #pragma unroll 8
        for (int j = 0; j < Hd; j++) acc = fmaf(sx[r][j], W_a[j * ACTD + a], acc);
        s_gi[r][a] = acc;
        out[(size_t)(row0 + r) * ACTD + a] = acc;
    }
    __syncthreads();
    for (int idx = tid; idx < Rr * Hd; idx += SCAN_THREADS) {   // phi_logits
        int j = idx & 63, r = idx >> 6;
        float acc = b_act[j];
        #pragma unroll
        for (int a = 0; a < ACTD; a++) acc = fmaf(s_gi[r][a], W_act[a * Hd + j], acc);
        s_mp[r][j] = fmaxf(acc, 0.0f);
    }
    __syncthreads();
    if (tid < Rr) {
        int r = tid;
        float acc = b_durd[0];
        for (int j = 0; j < Hd; j++) acc = fmaf(s_mp[r][j], W_durd[j], acc);
        for (int j = 0; j < Hd; j++) acc = fmaf(sx[r][j],  W_durd[Hd + j], acc);
        out[(size_t)Bn * ACTD + row0 + r] = acc;
        out[(size_t)Bn * ACTD + Bn + row0 + r] = softplusf(acc);
        g_kld[row0 + r] = s_kld[r];
    }
}

// ---------------- kernel 4: kld mean ----------------
__global__ void __launch_bounds__(256) kld_reduce_kernel(float* __restrict__ out) {
    __shared__ float s[256];
    int tid = threadIdx.x;
    s[tid] = g_kld[tid] + g_kld[tid + 256] + g_kld[tid + 512] + g_kld[tid + 768];
    __syncthreads();
    for (int st = 128; st > 0; st >>= 1) {
        if (tid < st) s[tid] += s[tid + st];
        __syncthreads();
    }
    if (tid == 0) out[(size_t)Bn * ACTD + 2 * Bn] = s[0] * (1.0f / Bn);
}

// ---------------- launch ----------------
extern "C" void kernel_launch(void* const* d_in, const int* in_sizes, int n_in,
                              void* d_out, int out_size) {
    const int*   acts   = (const int*)  d_in[0];
    const float* durs   = (const float*)d_in[1];
    const float* W_act  = (const float*)d_in[2];
    const float* b_act  = (const float*)d_in[3];
    const float* W_dur  = (const float*)d_in[4];
    const float* b_dur  = (const float*)d_in[5];
    const float* W_x    = (const float*)d_in[6];
    const float* b_x    = (const float*)d_in[7];
    const float* W_z    = (const float*)d_in[8];
    const float* b_z    = (const float*)d_in[9];
    const float* Wp1    = (const float*)d_in[10];
    const float* bp1    = (const float*)d_in[11];
    const float* Wp2    = (const float*)d_in[12];
    const float* bp2    = (const float*)d_in[13];
    const float* Wq1    = (const float*)d_in[14];
    const float* bq1    = (const float*)d_in[15];
    const float* Wq2    = (const float*)d_in[16];
    const float* bq2    = (const float*)d_in[17];
    const float* W_dec  = (const float*)d_in[18];
    const float* b_dec  = (const float*)d_in[19];
    const float* W_a    = (const float*)d_in[20];
    const float* b_a    = (const float*)d_in[21];
    const float* W_durd = (const float*)d_in[22];
    const float* b_durd = (const float*)d_in[23];
    const float* W_ih   = (const float*)d_in[24];
    const float* W_hh   = (const float*)d_in[25];
    const float* b_ih   = (const float*)d_in[26];
    const float* b_hh   = (const float*)d_in[27];
    const float* gpost  = (const float*)d_in[28];
    const float* gprior = (const float*)d_in[29];
    float* out = (float*)d_out;

    // eps precompute: 129*1024*64 threads, 1000 threefry blocks each (partitionable scheme)
    eps_kernel<<<((Tn + 1) * Bn * Hd) / 256, 256>>>();
    // embeddings
    embed_kernel<<<Bn * Tn, 64>>>(acts, durs, W_act, b_act, W_dur, b_dur, W_x, b_x);
    // sequential scan, parallel over batch
    scan_kernel<<<Bn / Rr, SCAN_THREADS>>>(
        W_act, b_act, W_z, b_z, Wp1, bp1, Wp2, bp2, Wq1, bq1, Wq2, bq2,
        W_dec, b_dec, W_a, b_a, W_durd, b_durd, W_ih, W_hh, b_ih, b_hh,
        gpost, gprior, out);
    // kld mean
    kld_reduce_kernel<<<1, 256>>>(out);
}

// round 3
// speedup vs baseline: 1.0122x; 1.0122x over previous
#include <cuda_runtime.h>

#define Bn 1024
#define Tn 128
#define Hd 64
#define NZv 5
#define ACTD 20
#define Rr 8
#define SCAN_THREADS 256

// ---------------- device scratch (static allocation only) ----------------
__device__ float g_phix[(size_t)Tn * Bn * Hd];          // (T,B,H)
__device__ float g_eps[(size_t)(Tn + 1) * Bn * Hd];     // (T+1,B,H)
__device__ float g_kld[Bn];

// ---------------- math helpers ----------------
__device__ __forceinline__ float softplusf(float x) {
    return fmaxf(x, 0.0f) + log1pf(expf(-fabsf(x)));
}
__device__ __forceinline__ float sigmoidf(float x) {
    return 1.0f / (1.0f + expf(-x));
}

// XLA ErfInv32 (Giles) polynomial
__device__ __forceinline__ float erfinv_f(float x) {
    float w = -__logf(fmaf(-x, x, 1.0f));   // -log((1-x)(1+x)) = -log(1-x^2)
    float p;
    if (w < 5.0f) {
        w = w - 2.5f;
        p = 2.81022636e-08f;
        p = fmaf(p, w, 3.43273939e-07f);
        p = fmaf(p, w, -3.5233877e-06f);
        p = fmaf(p, w, -4.39150654e-06f);
        p = fmaf(p, w, 0.00021858087f);
        p = fmaf(p, w, -0.00125372503f);
        p = fmaf(p, w, -0.00417768164f);
        p = fmaf(p, w, 0.246640727f);
        p = fmaf(p, w, 1.50140941f);
    } else {
        w = sqrtf(w) - 3.0f;
        p = -0.000200214257f;
        p = fmaf(p, w, 0.000100950558f);
        p = fmaf(p, w, 0.00134934322f);
        p = fmaf(p, w, -0.00367342844f);
        p = fmaf(p, w, 0.00573950773f);
        p = fmaf(p, w, -0.0076224613f);
        p = fmaf(p, w, 0.00943887047f);
        p = fmaf(p, w, 1.00167406f);
        p = fmaf(p, w, 2.83297682f);
    }
    return p * x;
}

// JAX threefry2x32 (20 rounds, key injection every 4) — general version (prologue use)
__device__ __forceinline__ uint2 threefry2x32(unsigned k0, unsigned k1,
                                              unsigned x0, unsigned x1) {
    unsigned ks2 = k0 ^ k1 ^ 0x1BD11BDAu;
#define TF_RND(r) { x0 += x1; x1 = __funnelshift_l(x1, x1, r); x1 ^= x0; }
    x0 += k0; x1 += k1;
    TF_RND(13) TF_RND(15) TF_RND(26) TF_RND(6)
    x0 += k1;  x1 += ks2 + 1u;
    TF_RND(17) TF_RND(29) TF_RND(16) TF_RND(24)
    x0 += ks2; x1 += k0 + 2u;
    TF_RND(13) TF_RND(15) TF_RND(26) TF_RND(6)
    x0 += k0;  x1 += k1 + 3u;
    TF_RND(17) TF_RND(29) TF_RND(16) TF_RND(24)
    x0 += k1;  x1 += ks2 + 4u;
    TF_RND(13) TF_RND(15) TF_RND(26) TF_RND(6)
    x0 += ks2; x1 += k0 + 5u;
#undef TF_RND
    uint2 r; r.x = x0; r.y = x1; return r;
}

// Specialized: counter word0 == 0, returns y0 ^ y1.
// c1..c5 are the precomputed second-word key injections.
__device__ __forceinline__ unsigned tf_xor(
    unsigned k0, unsigned k1, unsigned ks2,
    unsigned c1, unsigned c2, unsigned c3, unsigned c4, unsigned c5,
    unsigned e)
{
    unsigned x0 = k0;          // 0 + k0
    unsigned x1 = e + k1;
#define TF_RND(r) { x0 += x1; x1 = __funnelshift_l(x1, x1, r); x1 ^= x0; }
    TF_RND(13) TF_RND(15) TF_RND(26) TF_RND(6)
    x0 += k1;  x1 += c1;
    TF_RND(17) TF_RND(29) TF_RND(16) TF_RND(24)
    x0 += ks2; x1 += c2;
    TF_RND(13) TF_RND(15) TF_RND(26) TF_RND(6)
    x0 += k0;  x1 += c3;
    TF_RND(17) TF_RND(29) TF_RND(16) TF_RND(24)
    x0 += k1;  x1 += c4;
    TF_RND(13) TF_RND(15) TF_RND(26) TF_RND(6)
    x0 += ks2; x1 += c5;
#undef TF_RND
    return x0 ^ x1;
}

// bits -> JAX uniform(-0.99999994, 1.0) -> sqrt(2)*erfinv
__device__ __forceinline__ float normal_from_bits(unsigned bits) {
    float f = __uint_as_float((bits >> 9) | 0x3F800000u) - 1.0f;  // [0,1)
    float u = fmaf(f, 2.0f, -0.99999994f);
    u = fmaxf(u, -0.99999994f);
    return 1.41421356f * erfinv_f(u);
}

// ---------------- kernel 1: eps precompute (129 x 1024 x 64) ----------------
// JAX threefry_partitionable: bits[e] = y0 ^ y1, counter = (0, e).
__global__ void __launch_bounds__(256) eps_kernel() {
    int gid = blockIdx.x * blockDim.x + threadIdx.x;
    int t = gid >> 16;                 // Bn*Hd = 65536 elements per timestep
    unsigned bz = (unsigned)(gid & 0xFFFF);
    uint2 kk = threefry2x32(0u, 42u, 0u, (unsigned)t);   // fold_in(key(42), t)
    const unsigned k0 = kk.x, k1 = kk.y;
    const unsigned ks2 = k0 ^ k1 ^ 0x1BD11BDAu;
    const unsigned c1 = ks2 + 1u, c2 = k0 + 2u, c3 = k1 + 3u,
                   c4 = ks2 + 4u, c5 = k0 + 5u;

    float sum0 = 0.0f, sum1 = 0.0f, sum2 = 0.0f, sum3 = 0.0f;
    unsigned e0 = bz, e1 = bz + 65536u, e2 = bz + 131072u, e3 = bz + 196608u;
    #pragma unroll 2
    for (int s = 0; s < 250; s++) {    // 4 independent cipher chains for ILP
        unsigned b0 = tf_xor(k0, k1, ks2, c1, c2, c3, c4, c5, e0);
        unsigned b1 = tf_xor(k0, k1, ks2, c1, c2, c3, c4, c5, e1);
        unsigned b2 = tf_xor(k0, k1, ks2, c1, c2, c3, c4, c5, e2);
        unsigned b3 = tf_xor(k0, k1, ks2, c1, c2, c3, c4, c5, e3);
        sum0 += normal_from_bits(b0);
        sum1 += normal_from_bits(b1);
        sum2 += normal_from_bits(b2);
        sum3 += normal_from_bits(b3);
        e0 += 262144u; e1 += 262144u; e2 += 262144u; e3 += 262144u;
    }
    g_eps[gid] = ((sum0 + sum1) + (sum2 + sum3)) * 0.001f;
}

// ---------------- kernel 2: per-(b,t) embedding -> phi_x (T,B,H) ----------------
__global__ void __launch_bounds__(64) embed_kernel(
    const int* __restrict__ acts, const float* __restrict__ durs,
    const float* __restrict__ W_act, const float* __restrict__ b_act,
    const float* __restrict__ W_dur, const float* __restrict__ b_dur,
    const float* __restrict__ W_x, const float* __restrict__ b_x)
{
    __shared__ float inp[2 * Hd];
    int rid = blockIdx.x;             // 0..B*T-1
    int b = rid / Tn, t = rid % Tn;
    int j = threadIdx.x;
    int a = acts[b * Tn + t];
    float du = durs[b * Tn + t];
    inp[j]      = fmaxf(W_act[a * Hd + j] + b_act[j], 0.0f);
    inp[Hd + j] = fmaxf(fmaf(du, W_dur[j], b_dur[j]), 0.0f);
    __syncthreads();
    float acc = b_x[j];
    #pragma unroll 16
    for (int i = 0; i < 2 * Hd; i++) acc = fmaf(inp[i], W_x[i * Hd + j], acc);
    g_phix[((size_t)t * Bn + b) * Hd + j] = fmaxf(acc, 0.0f);
}

// ---------------- kernel 3: sequential scan, parallel over batch rows ----------------
__global__ void __launch_bounds__(SCAN_THREADS) scan_kernel(
    const float* __restrict__ W_act, const float* __restrict__ b_act,
    const float* __restrict__ W_z,  const float* __restrict__ b_z,
    const float* __restrict__ Wp1,  const float* __restrict__ bp1,
    const float* __restrict__ Wp2,  const float* __restrict__ bp2,
    const float* __restrict__ Wq1,  const float* __restrict__ bq1,
    const float* __restrict__ Wq2,  const float* __restrict__ bq2,
    const float* __restrict__ W_dec,const float* __restrict__ b_dec,
    const float* __restrict__ W_a,  const float* __restrict__ b_a,
    const float* __restrict__ W_durd,const float* __restrict__ b_durd,
    const float* __restrict__ W_ih, const float* __restrict__ W_hh,
    const float* __restrict__ b_ih, const float* __restrict__ b_hh,
    const float* __restrict__ gpost,const float* __restrict__ gprior,
    float* __restrict__ out)
{
    __shared__ float sh[Rr][Hd];            // h
    __shared__ float sx[Rr][Hd];            // phi_x (reused as dec in epilogue)
    __shared__ float s_h1[Rr][NZv][Hd];     // mixture hidden (post, then prior)
    __shared__ float s_mp[Rr][Hd];          // m_post (reused as phi_logits)
    __shared__ float s_mq[Rr][Hd];          // m_prior
    __shared__ float s_z[Rr][Hd];           // z
    __shared__ float s_pz[Rr][Hd];          // phi_z
    __shared__ float s_gi[Rr][3 * Hd];      // GRU input gates (reused as logits)
    __shared__ float s_gh[Rr][3 * Hd];      // GRU hidden gates
    __shared__ float s_kld[Rr];

    const int tid = threadIdx.x;
    const int row0 = blockIdx.x * Rr;

    for (int idx = tid; idx < Rr * Hd; idx += SCAN_THREADS)
        sh[idx >> 6][idx & 63] = 0.0f;
    if (tid < Rr) s_kld[tid] = 0.0f;
    __syncthreads();

    for (int t = 0; t < Tn; t++) {
        for (int idx = tid; idx < Rr * Hd; idx += SCAN_THREADS) {
            int r = idx >> 6, j = idx & 63;
            sx[r][j] = g_phix[((size_t)t * Bn + row0 + r) * Hd + j];
        }
        __syncthreads();

        // S1: posterior mixture hidden
        for (int idx = tid; idx < Rr * NZv * Hd; idx += SCAN_THREADS) {
            int o = idx & 63, n = (idx >> 6) % NZv, r = idx / (NZv * Hd);
            const float* w = Wp1 + (size_t)n * 128 * Hd + o;
            float acc = bp1[n * Hd + o];
            #pragma unroll 8
            for (int i = 0; i < Hd; i++) acc = fmaf(sx[r][i], w[i * Hd], acc);
            #pragma unroll 8
            for (int i = 0; i < Hd; i++) acc = fmaf(sh[r][i], w[(Hd + i) * Hd], acc);
            s_h1[r][n][o] = fmaxf(acc, 0.0f);
        }
        __syncthreads();

        // S2: m_post
        for (int idx = tid; idx < Rr * Hd; idx += SCAN_THREADS) {
            int zc = idx & 63, r = idx >> 6;
            float m = 0.0f;
            for (int n = 0; n < NZv; n++) {
                const float* w = Wp2 + (size_t)n * Hd * Hd + zc;
                float acc = bp2[n * Hd + zc];
                #pragma unroll 8
                for (int o = 0; o < Hd; o++) acc = fmaf(s_h1[r][n][o], w[o * Hd], acc);
                m = fmaf(gpost[n], acc, m);
            }
            s_mp[r][zc] = m;
        }
        __syncthreads();

        // S3: prior mixture hidden
        for (int idx = tid; idx < Rr * NZv * Hd; idx += SCAN_THREADS) {
            int o = idx & 63, n = (idx >> 6) % NZv, r = idx / (NZv * Hd);
            const float* w = Wq1 + (size_t)n * Hd * Hd + o;
            float acc = bq1[n * Hd + o];
            #pragma unroll 8
            for (int i = 0; i < Hd; i++) acc = fmaf(sh[r][i], w[i * Hd], acc);
            s_h1[r][n][o] = fmaxf(acc, 0.0f);
        }
        __syncthreads();

        // S4: m_prior
        for (int idx = tid; idx < Rr * Hd; idx += SCAN_THREADS) {
            int zc = idx & 63, r = idx >> 6;
            float m = 0.0f;
            for (int n = 0; n < NZv; n++) {
                const float* w = Wq2 + (size_t)n * Hd * Hd + zc;
                float acc = bq2[n * Hd + zc];
                #pragma unroll 8
                for (int o = 0; o < Hd; o++) acc = fmaf(s_h1[r][n][o], w[o * Hd], acc);
                m = fmaf(gprior[n], acc, m);
            }
            s_mq[r][zc] = m;
        }
        __syncthreads();

        // S5: KL + z
        for (int idx = tid; idx < Rr * Hd; idx += SCAN_THREADS) {
            int zc = idx & 63, r = idx >> 6;
            float mp = s_mp[r][zc], mq = s_mq[r][zc];
            float pm = fmaxf(mp, 0.0f), qm = fmaxf(mq, 0.0f);
            float ps = softplusf(mp),   qs = softplusf(mq);
            float d = pm - qm;
            float kt = logf(qs / ps) + (ps * ps + d * d) / (2.0f * qs * qs) - 0.5f;
            atomicAdd(&s_kld[r], kt);
            float e = g_eps[((size_t)t * Bn + row0 + r) * Hd + zc];
            s_z[r][zc] = fmaf(ps, e, pm);
        }
        __syncthreads();

        // S6: phi_z
        for (int idx = tid; idx < Rr * Hd; idx += SCAN_THREADS) {
            int j = idx & 63, r = idx >> 6;
            float acc = b_z[j];
            #pragma unroll 8
            for (int i = 0; i < Hd; i++) acc = fmaf(s_z[r][i], W_z[i * Hd + j], acc);
            s_pz[r][j] = fmaxf(acc, 0.0f);
        }
        __syncthreads();

        // S7: GRU gates
        for (int idx = tid; idx < Rr * 3 * Hd; idx += SCAN_THREADS) {
            int k = idx % (3 * Hd), r = idx / (3 * Hd);
            const float* wih = W_ih + k;
            float a1 = b_ih[k];
            #pragma unroll 8
            for (int i = 0; i < Hd; i++) a1 = fmaf(sx[r][i],  wih[i * 3 * Hd], a1);
            #pragma unroll 8
            for (int i = 0; i < Hd; i++) a1 = fmaf(s_pz[r][i], wih[(Hd + i) * 3 * Hd], a1);
            s_gi[r][k] = a1;
            const float* whh = W_hh + k;
            float a2 = b_hh[k];
            #pragma unroll 8
            for (int i = 0; i < Hd; i++) a2 = fmaf(sh[r][i], whh[i * 3 * Hd], a2);
            s_gh[r][k] = a2;
        }
        __syncthreads();

        // S8: h update
        for (int idx = tid; idx < Rr * Hd; idx += SCAN_THREADS) {
            int j = idx & 63, r = idx >> 6;
            float ir = s_gi[r][j], iz = s_gi[r][Hd + j], in_ = s_gi[r][2 * Hd + j];
            float hr = s_gh[r][j], hz = s_gh[r][Hd + j], hn  = s_gh[r][2 * Hd + j];
            float rg = sigmoidf(ir + hr);
            float zz = sigmoidf(iz + hz);
            float nn = tanhf(fmaf(rg, hn, in_));
            sh[r][j] = (1.0f - zz) * nn + zz * sh[r][j];
        }
        __syncthreads();
    }

    // ---------- epilogue ----------
    for (int idx = tid; idx < Rr * NZv * Hd; idx += SCAN_THREADS) {
        int o = idx & 63, n = (idx >> 6) % NZv, r = idx / (NZv * Hd);
        const float* w = Wq1 + (size_t)n * Hd * Hd + o;
        float acc = bq1[n * Hd + o];
        #pragma unroll 8
        for (int i = 0; i < Hd; i++) acc = fmaf(sh[r][i], w[i * Hd], acc);
        s_h1[r][n][o] = fmaxf(acc, 0.0f);
    }
    __syncthreads();
    for (int idx = tid; idx < Rr * Hd; idx += SCAN_THREADS) {
        int zc = idx & 63, r = idx >> 6;
        float m = 0.0f;
        for (int n = 0; n < NZv; n++) {
            const float* w = Wq2 + (size_t)n * Hd * Hd + zc;
            float acc = bq2[n * Hd + zc];
            #pragma unroll 8
            for (int o = 0; o < Hd; o++) acc = fmaf(s_h1[r][n][o], w[o * Hd], acc);
            m = fmaf(gprior[n], acc, m);
        }
        float qm = fmaxf(m, 0.0f), qs = softplusf(m);
        float e = g_eps[((size_t)Tn * Bn + row0 + r) * Hd + zc];
        s_z[r][zc] = fmaf(qs, e, qm);
    }
    __syncthreads();
    for (int idx = tid; idx < Rr * Hd; idx += SCAN_THREADS) {   // phi_z
        int j = idx & 63, r = idx >> 6;
        float acc = b_z[j];
        #pragma unroll 8
        for (int i = 0; i < Hd; i++) acc = fmaf(s_z[r][i], W_z[i * Hd + j], acc);
        s_pz[r][j] = fmaxf(acc, 0.0f);
    }
    __syncthreads();
    for (int idx = tid; idx < Rr * Hd; idx += SCAN_THREADS) {   // dec
        int j = idx & 63, r = idx >> 6;
        float acc = b_dec[j];
        #pragma unroll 8
        for (int i = 0; i < Hd; i++) acc = fmaf(s_pz[r][i], W_dec[i * Hd + j], acc);
        #pragma unroll 8
        for (int i = 0; i < Hd; i++) acc = fmaf(sh[r][i],  W_dec[(Hd + i) * Hd + j], acc);
        sx[r][j] = fmaxf(acc, 0.0f);
    }
    __syncthreads();
    for (int idx = tid; idx < Rr * ACTD; idx += SCAN_THREADS) {  // logits
        int a = idx % ACTD, r = idx / ACTD;
        float acc = b_a[a];
        #pragma unroll 8
        for (int j = 0; j < Hd; j++) acc = fmaf(sx[r][j], W_a[j * ACTD + a], acc);
        s_gi[r][a] = acc;
        out[(size_t)(row0 + r) * ACTD + a] = acc;
    }
    __syncthreads();
    for (int idx = tid; idx < Rr * Hd; idx += SCAN_THREADS) {   // phi_logits
        int j = idx & 63, r = idx >> 6;
        float acc = b_act[j];
        #pragma unroll
        for (int a = 0; a < ACTD; a++) acc = fmaf(s_gi[r][a], W_act[a * Hd + j], acc);
        s_mp[r][j] = fmaxf(acc, 0.0f);
    }
    __syncthreads();
    if (tid < Rr) {
        int r = tid;
        float acc = b_durd[0];
        for (int j = 0; j < Hd; j++) acc = fmaf(s_mp[r][j], W_durd[j], acc);
        for (int j = 0; j < Hd; j++) acc = fmaf(sx[r][j],  W_durd[Hd + j], acc);
        out[(size_t)Bn * ACTD + row0 + r] = acc;
        out[(size_t)Bn * ACTD + Bn + row0 + r] = softplusf(acc);
        g_kld[row0 + r] = s_kld[r];
    }
}

// ---------------- kernel 4: kld mean ----------------
__global__ void __launch_bounds__(256) kld_reduce_kernel(float* __restrict__ out) {
    __shared__ float s[256];
    int tid = threadIdx.x;
    s[tid] = g_kld[tid] + g_kld[tid + 256] + g_kld[tid + 512] + g_kld[tid + 768];
    __syncthreads();
    for (int st = 128; st > 0; st >>= 1) {
        if (tid < st) s[tid] += s[tid + st];
        __syncthreads();
    }
    if (tid == 0) out[(size_t)Bn * ACTD + 2 * Bn] = s[0] * (1.0f / Bn);
}

// ---------------- launch ----------------
extern "C" void kernel_launch(void* const* d_in, const int* in_sizes, int n_in,
                              void* d_out, int out_size) {
    const int*   acts   = (const int*)  d_in[0];
    const float* durs   = (const float*)d_in[1];
    const float* W_act  = (const float*)d_in[2];
    const float* b_act  = (const float*)d_in[3];
    const float* W_dur  = (const float*)d_in[4];
    const float* b_dur  = (const float*)d_in[5];
    const float* W_x    = (const float*)d_in[6];
    const float* b_x    = (const float*)d_in[7];
    const float* W_z    = (const float*)d_in[8];
    const float* b_z    = (const float*)d_in[9];
    const float* Wp1    = (const float*)d_in[10];
    const float* bp1    = (const float*)d_in[11];
    const float* Wp2    = (const float*)d_in[12];
    const float* bp2    = (const float*)d_in[13];
    const float* Wq1    = (const float*)d_in[14];
    const float* bq1    = (const float*)d_in[15];
    const float* Wq2    = (const float*)d_in[16];
    const float* bq2    = (const float*)d_in[17];
    const float* W_dec  = (const float*)d_in[18];
    const float* b_dec  = (const float*)d_in[19];
    const float* W_a    = (const float*)d_in[20];
    const float* b_a    = (const float*)d_in[21];
    const float* W_durd = (const float*)d_in[22];
    const float* b_durd = (const float*)d_in[23];
    const float* W_ih   = (const float*)d_in[24];
    const float* W_hh   = (const float*)d_in[25];
    const float* b_ih   = (const float*)d_in[26];
    const float* b_hh   = (const float*)d_in[27];
    const float* gpost  = (const float*)d_in[28];
    const float* gprior = (const float*)d_in[29];
    float* out = (float*)d_out;

    eps_kernel<<<((Tn + 1) * Bn * Hd) / 256, 256>>>();
    embed_kernel<<<Bn * Tn, 64>>>(acts, durs, W_act, b_act, W_dur, b_dur, W_x, b_x);
    scan_kernel<<<Bn / Rr, SCAN_THREADS>>>(
        W_act, b_act, W_z, b_z, Wp1, bp1, Wp2, bp2, Wq1, bq1, Wq2, bq2,
        W_dec, b_dec, W_a, b_a, W_durd, b_durd, W_ih, W_hh, b_ih, b_hh,
        gpost, gprior, out);
    kld_reduce_kernel<<<1, 256>>>(out);
}

// round 4
// speedup vs baseline: 1.2859x; 1.2704x over previous
#include <cuda_runtime.h>

#define Bn 1024
#define Tn 128
#define Hd 64
#define NZv 5
#define ACTD 20
#define Rr 8

// ---------------- device scratch (static allocation only) ----------------
__device__ float g_phix[(size_t)Tn * Bn * Hd];          // (T,B,H)
__device__ float g_eps[(size_t)(Tn + 1) * Bn * Hd];     // (T+1,B,H)
__device__ float g_kld[Bn];
__device__ unsigned g_one = 1;   // runtime-opaque 1: forces adds onto IMAD (fma pipe)

// ---------------- math helpers ----------------
__device__ __forceinline__ float softplusf(float x) {
    return fmaxf(x, 0.0f) + log1pf(expf(-fabsf(x)));
}
__device__ __forceinline__ float sigmoidf(float x) {
    return 1.0f / (1.0f + expf(-x));
}

// add via IMAD so it issues on the fma pipe (alu pipe is the bottleneck)
__device__ __forceinline__ unsigned imadd(unsigned a, unsigned b, unsigned one) {
    unsigned d;
    asm("mad.lo.u32 %0, %1, %2, %3;" : "=r"(d) : "r"(a), "r"(one), "r"(b));
    return d;
}

// XLA ErfInv32 (Giles) polynomial
__device__ __forceinline__ float erfinv_f(float x) {
    float w = -__logf(fmaf(-x, x, 1.0f));
    float p;
    if (w < 5.0f) {
        w = w - 2.5f;
        p = 2.81022636e-08f;
        p = fmaf(p, w, 3.43273939e-07f);
        p = fmaf(p, w, -3.5233877e-06f);
        p = fmaf(p, w, -4.39150654e-06f);
        p = fmaf(p, w, 0.00021858087f);
        p = fmaf(p, w, -0.00125372503f);
        p = fmaf(p, w, -0.00417768164f);
        p = fmaf(p, w, 0.246640727f);
        p = fmaf(p, w, 1.50140941f);
    } else {
        w = sqrtf(w) - 3.0f;
        p = -0.000200214257f;
        p = fmaf(p, w, 0.000100950558f);
        p = fmaf(p, w, 0.00134934322f);
        p = fmaf(p, w, -0.00367342844f);
        p = fmaf(p, w, 0.00573950773f);
        p = fmaf(p, w, -0.0076224613f);
        p = fmaf(p, w, 0.00943887047f);
        p = fmaf(p, w, 1.00167406f);
        p = fmaf(p, w, 2.83297682f);
    }
    return p * x;
}

// general threefry (prologue key fold only)
__device__ __forceinline__ uint2 threefry2x32(unsigned k0, unsigned k1,
                                              unsigned x0, unsigned x1) {
    unsigned ks2 = k0 ^ k1 ^ 0x1BD11BDAu;
#define TF_RND(r) { x0 += x1; x1 = __funnelshift_l(x1, x1, r); x1 ^= x0; }
    x0 += k0; x1 += k1;
    TF_RND(13) TF_RND(15) TF_RND(26) TF_RND(6)
    x0 += k1;  x1 += ks2 + 1u;
    TF_RND(17) TF_RND(29) TF_RND(16) TF_RND(24)
    x0 += ks2; x1 += k0 + 2u;
    TF_RND(13) TF_RND(15) TF_RND(26) TF_RND(6)
    x0 += k0;  x1 += k1 + 3u;
    TF_RND(17) TF_RND(29) TF_RND(16) TF_RND(24)
    x0 += k1;  x1 += ks2 + 4u;
    TF_RND(13) TF_RND(15) TF_RND(26) TF_RND(6)
    x0 += ks2; x1 += k0 + 5u;
#undef TF_RND
    uint2 r; r.x = x0; r.y = x1; return r;
}

// specialized hot path: counter word0 == 0, all adds on the fma pipe, returns y0^y1
__device__ __forceinline__ unsigned tf_xor(
    unsigned k0, unsigned k1, unsigned ks2,
    unsigned c1, unsigned c2, unsigned c3, unsigned c4, unsigned c5,
    unsigned e, unsigned one)
{
    unsigned x0 = k0;
    unsigned x1 = imadd(e, k1, one);
#define TF_RND(r) { x0 = imadd(x1, x0, one); x1 = __funnelshift_l(x1, x1, r); x1 ^= x0; }
    TF_RND(13) TF_RND(15) TF_RND(26) TF_RND(6)
    x0 = imadd(k1, x0, one);  x1 = imadd(c1, x1, one);
    TF_RND(17) TF_RND(29) TF_RND(16) TF_RND(24)
    x0 = imadd(ks2, x0, one); x1 = imadd(c2, x1, one);
    TF_RND(13) TF_RND(15) TF_RND(26) TF_RND(6)
    x0 = imadd(k0, x0, one);  x1 = imadd(c3, x1, one);
    TF_RND(17) TF_RND(29) TF_RND(16) TF_RND(24)
    x0 = imadd(k1, x0, one);  x1 = imadd(c4, x1, one);
    TF_RND(13) TF_RND(15) TF_RND(26) TF_RND(6)
    x0 = imadd(ks2, x0, one); x1 = imadd(c5, x1, one);
#undef TF_RND
    return x0 ^ x1;
}

__device__ __forceinline__ float normal_from_bits(unsigned bits) {
    float f = __uint_as_float((bits >> 9) | 0x3F800000u) - 1.0f;  // [0,1)
    float u = fmaf(f, 2.0f, -0.99999994f);
    u = fmaxf(u, -0.99999994f);
    return 1.41421356f * erfinv_f(u);
}

// ---------------- kernel 1: eps precompute (129 x 1024 x 64) ----------------
__global__ void __launch_bounds__(256) eps_kernel() {
    int gid = blockIdx.x * blockDim.x + threadIdx.x;
    int t = gid >> 16;
    unsigned bz = (unsigned)(gid & 0xFFFF);
    const unsigned one = g_one;
    uint2 kk = threefry2x32(0u, 42u, 0u, (unsigned)t);   // fold_in(key(42), t)
    const unsigned k0 = kk.x, k1 = kk.y;
    const unsigned ks2 = k0 ^ k1 ^ 0x1BD11BDAu;
    const unsigned c1 = ks2 + 1u, c2 = k0 + 2u, c3 = k1 + 3u,
                   c4 = ks2 + 4u, c5 = k0 + 5u;

    float sum0 = 0.0f, sum1 = 0.0f, sum2 = 0.0f, sum3 = 0.0f;
    unsigned e0 = bz, e1 = bz + 65536u, e2 = bz + 131072u, e3 = bz + 196608u;
    const unsigned step = 262144u;
    #pragma unroll 2
    for (int s = 0; s < 250; s++) {
        unsigned b0 = tf_xor(k0, k1, ks2, c1, c2, c3, c4, c5, e0, one);
        unsigned b1 = tf_xor(k0, k1, ks2, c1, c2, c3, c4, c5, e1, one);
        unsigned b2 = tf_xor(k0, k1, ks2, c1, c2, c3, c4, c5, e2, one);
        unsigned b3 = tf_xor(k0, k1, ks2, c1, c2, c3, c4, c5, e3, one);
        sum0 += normal_from_bits(b0);
        sum1 += normal_from_bits(b1);
        sum2 += normal_from_bits(b2);
        sum3 += normal_from_bits(b3);
        e0 = imadd(step, e0, one); e1 = imadd(step, e1, one);
        e2 = imadd(step, e2, one); e3 = imadd(step, e3, one);
    }
    g_eps[gid] = ((sum0 + sum1) + (sum2 + sum3)) * 0.001f;
}

// ---------------- kernel 2: embedding, 8 rows/block, register tiled ----------------
__global__ void __launch_bounds__(128) embed_kernel(
    const int* __restrict__ acts, const float* __restrict__ durs,
    const float* __restrict__ W_act, const float* __restrict__ b_act,
    const float* __restrict__ W_dur, const float* __restrict__ b_dur,
    const float* __restrict__ W_x, const float* __restrict__ b_x)
{
    __shared__ float inp[8][2 * Hd];
    const int tid = threadIdx.x;
    const int rid0 = blockIdx.x * 8;
    const int b = rid0 >> 7;          // rows share b (8 | 128)
    const int t0 = rid0 & 127;
    const int c = tid;                // 0..127
    #pragma unroll
    for (int rr = 0; rr < 8; rr++) {
        if (c < Hd) {
            int a = acts[b * Tn + t0 + rr];
            inp[rr][c] = fmaxf(W_act[a * Hd + c] + b_act[c], 0.0f);
        } else {
            float du = durs[b * Tn + t0 + rr];
            inp[rr][c] = fmaxf(fmaf(du, W_dur[c - Hd], b_dur[c - Hd]), 0.0f);
        }
    }
    __syncthreads();
    // phi_x = relu(inp @ W_x + b_x): units (j2, r) = 256, 2 passes of 128 threads
    #pragma unroll
    for (int p = 0; p < 2; p++) {
        int u = tid + p * 128;
        int r = u >> 5, j0 = (u & 31) * 2;
        float a0 = b_x[j0], a1 = b_x[j0 + 1];
        const float2* w2 = (const float2*)(W_x + j0);
        #pragma unroll 8
        for (int i = 0; i < 2 * Hd; i++) {
            float xv = inp[r][i];
            float2 wv = w2[i * (Hd / 2)];
            a0 = fmaf(xv, wv.x, a0);
            a1 = fmaf(xv, wv.y, a1);
        }
        float* dst = g_phix + ((size_t)(t0 + r) * Bn + b) * Hd + j0;
        dst[0] = fmaxf(a0, 0.0f);
        dst[1] = fmaxf(a1, 0.0f);
    }
}

// ---------------- kernel 3: sequential scan, register-tiled matmuls ----------------
__global__ void __launch_bounds__(256) scan_kernel(
    const float* __restrict__ W_act, const float* __restrict__ b_act,
    const float* __restrict__ W_z,  const float* __restrict__ b_z,
    const float* __restrict__ Wp1,  const float* __restrict__ bp1,
    const float* __restrict__ Wp2,  const float* __restrict__ bp2,
    const float* __restrict__ Wq1,  const float* __restrict__ bq1,
    const float* __restrict__ Wq2,  const float* __restrict__ bq2,
    const float* __restrict__ W_dec,const float* __restrict__ b_dec,
    const float* __restrict__ W_a,  const float* __restrict__ b_a,
    const float* __restrict__ W_durd,const float* __restrict__ b_durd,
    const float* __restrict__ W_ih, const float* __restrict__ W_hh,
    const float* __restrict__ b_ih, const float* __restrict__ b_hh,
    const float* __restrict__ gpost,const float* __restrict__ gprior,
    float* __restrict__ out)
{
    __shared__ float sh[Rr][Hd];
    __shared__ float sx[Rr][Hd];            // phi_x; reused as dec in epilogue
    __shared__ float s_h1[Rr][NZv][Hd];
    __shared__ float s_mp[Rr][Hd];          // m_post; reused as phi_logits
    __shared__ float s_mq[Rr][Hd];
    __shared__ float s_z[Rr][Hd];
    __shared__ float s_pz[Rr][Hd];
    __shared__ float s_gi[Rr][3 * Hd];      // gi; reused as logits
    __shared__ float s_gh[Rr][3 * Hd];
    __shared__ float s_kld[Rr];

    const int tid = threadIdx.x;
    const int row0 = blockIdx.x * Rr;
    float kl_acc = 0.0f;

    if (tid < Rr * Hd / 4)
        ((float4*)sh)[tid] = make_float4(0.f, 0.f, 0.f, 0.f);
    __syncthreads();

    // (z2, r) decode used by several stages
    const int rS = tid >> 5;
    const int z0 = (tid & 31) * 2;

    for (int t = 0; t < Tn; t++) {
        if (tid < 128)
            ((float4*)sx)[tid] = ((const float4*)(g_phix + ((size_t)t * Bn + row0) * Hd))[tid];
        __syncthreads();

        // S1: h1 = relu([phi_x,h] @ Wp1[n] + bp1)  — units (r2, n, o4) = 320
        for (int u = tid; u < NZv * 16 * 4; u += 256) {
            int r2 = u / 80, rem = u % 80;
            int n = rem >> 4, o0 = (rem & 15) * 4;
            int r0 = r2 * 2;
            const float4* w4 = (const float4*)(Wp1 + (size_t)n * 128 * Hd + o0);
            float4 bb = *(const float4*)(bp1 + n * Hd + o0);
            float4 a0 = bb, a1 = bb;
            #pragma unroll 8
            for (int i = 0; i < Hd; i++) {
                float xa = sx[r0][i], xb = sx[r0 + 1][i];
                float4 wv = w4[i * 16];
                a0.x = fmaf(xa, wv.x, a0.x); a0.y = fmaf(xa, wv.y, a0.y);
                a0.z = fmaf(xa, wv.z, a0.z); a0.w = fmaf(xa, wv.w, a0.w);
                a1.x = fmaf(xb, wv.x, a1.x); a1.y = fmaf(xb, wv.y, a1.y);
                a1.z = fmaf(xb, wv.z, a1.z); a1.w = fmaf(xb, wv.w, a1.w);
            }
            #pragma unroll 8
            for (int i = 0; i < Hd; i++) {
                float xa = sh[r0][i], xb = sh[r0 + 1][i];
                float4 wv = w4[(Hd + i) * 16];
                a0.x = fmaf(xa, wv.x, a0.x); a0.y = fmaf(xa, wv.y, a0.y);
                a0.z = fmaf(xa, wv.z, a0.z); a0.w = fmaf(xa, wv.w, a0.w);
                a1.x = fmaf(xb, wv.x, a1.x); a1.y = fmaf(xb, wv.y, a1.y);
                a1.z = fmaf(xb, wv.z, a1.z); a1.w = fmaf(xb, wv.w, a1.w);
            }
            float* d0 = &s_h1[r0][n][o0];
            float* d1 = &s_h1[r0 + 1][n][o0];
            d0[0] = fmaxf(a0.x, 0.f); d0[1] = fmaxf(a0.y, 0.f); d0[2] = fmaxf(a0.z, 0.f); d0[3] = fmaxf(a0.w, 0.f);
            d1[0] = fmaxf(a1.x, 0.f); d1[1] = fmaxf(a1.y, 0.f); d1[2] = fmaxf(a1.z, 0.f); d1[3] = fmaxf(a1.w, 0.f);
        }
        __syncthreads();

        // S2: m_post — units (r, z2) = 256
        {
            float m0 = 0.f, m1 = 0.f;
            for (int n = 0; n < NZv; n++) {
                float t0a = bp2[n * Hd + z0], t1a = bp2[n * Hd + z0 + 1];
                const float2* w2 = (const float2*)(Wp2 + (size_t)n * Hd * Hd + z0);
                #pragma unroll 8
                for (int o = 0; o < Hd; o++) {
                    float hv = s_h1[rS][n][o];
                    float2 wv = w2[o * 32];
                    t0a = fmaf(hv, wv.x, t0a);
                    t1a = fmaf(hv, wv.y, t1a);
                }
                float g = gpost[n];
                m0 = fmaf(g, t0a, m0);
                m1 = fmaf(g, t1a, m1);
            }
            s_mp[rS][z0] = m0; s_mp[rS][z0 + 1] = m1;
        }
        __syncthreads();

        // S3: prior h1 = relu(h @ Wq1[n] + bq1) — units 320
        for (int u = tid; u < NZv * 16 * 4; u += 256) {
            int r2 = u / 80, rem = u % 80;
            int n = rem >> 4, o0 = (rem & 15) * 4;
            int r0 = r2 * 2;
            const float4* w4 = (const float4*)(Wq1 + (size_t)n * Hd * Hd + o0);
            float4 bb = *(const float4*)(bq1 + n * Hd + o0);
            float4 a0 = bb, a1 = bb;
            #pragma unroll 8
            for (int i = 0; i < Hd; i++) {
                float xa = sh[r0][i], xb = sh[r0 + 1][i];
                float4 wv = w4[i * 16];
                a0.x = fmaf(xa, wv.x, a0.x); a0.y = fmaf(xa, wv.y, a0.y);
                a0.z = fmaf(xa, wv.z, a0.z); a0.w = fmaf(xa, wv.w, a0.w);
                a1.x = fmaf(xb, wv.x, a1.x); a1.y = fmaf(xb, wv.y, a1.y);
                a1.z = fmaf(xb, wv.z, a1.z); a1.w = fmaf(xb, wv.w, a1.w);
            }
            float* d0 = &s_h1[r0][n][o0];
            float* d1 = &s_h1[r0 + 1][n][o0];
            d0[0] = fmaxf(a0.x, 0.f); d0[1] = fmaxf(a0.y, 0.f); d0[2] = fmaxf(a0.z, 0.f); d0[3] = fmaxf(a0.w, 0.f);
            d1[0] = fmaxf(a1.x, 0.f); d1[1] = fmaxf(a1.y, 0.f); d1[2] = fmaxf(a1.z, 0.f); d1[3] = fmaxf(a1.w, 0.f);
        }
        __syncthreads();

        // S4: m_prior — units (r, z2) = 256
        {
            float m0 = 0.f, m1 = 0.f;
            for (int n = 0; n < NZv; n++) {
                float t0a = bq2[n * Hd + z0], t1a = bq2[n * Hd + z0 + 1];
                const float2* w2 = (const float2*)(Wq2 + (size_t)n * Hd * Hd + z0);
                #pragma unroll 8
                for (int o = 0; o < Hd; o++) {
                    float hv = s_h1[rS][n][o];
                    float2 wv = w2[o * 32];
                    t0a = fmaf(hv, wv.x, t0a);
                    t1a = fmaf(hv, wv.y, t1a);
                }
                float g = gprior[n];
                m0 = fmaf(g, t0a, m0);
                m1 = fmaf(g, t1a, m1);
            }
            s_mq[rS][z0] = m0; s_mq[rS][z0 + 1] = m1;
        }
        __syncthreads();

        // S5: KL (register accumulate) + z — units (r, z2) = 256
        {
            const float* ep = g_eps + ((size_t)t * Bn + row0 + rS) * Hd + z0;
            #pragma unroll
            for (int q = 0; q < 2; q++) {
                float mp = s_mp[rS][z0 + q], mq = s_mq[rS][z0 + q];
                float pm = fmaxf(mp, 0.0f), qm = fmaxf(mq, 0.0f);
                float ps = softplusf(mp),   qs = softplusf(mq);
                float d = pm - qm;
                kl_acc += logf(qs / ps) + (ps * ps + d * d) / (2.0f * qs * qs) - 0.5f;
                s_z[rS][z0 + q] = fmaf(ps, ep[q], pm);
            }
        }
        __syncthreads();

        // S6: phi_z = relu(z @ W_z + b_z) — units (r, j2) = 256
        {
            float a0 = b_z[z0], a1 = b_z[z0 + 1];
            const float2* w2 = (const float2*)(W_z + z0);
            #pragma unroll 8
            for (int i = 0; i < Hd; i++) {
                float xv = s_z[rS][i];
                float2 wv = w2[i * 32];
                a0 = fmaf(xv, wv.x, a0);
                a1 = fmaf(xv, wv.y, a1);
            }
            s_pz[rS][z0] = fmaxf(a0, 0.f);
            s_pz[rS][z0 + 1] = fmaxf(a1, 0.f);
        }
        __syncthreads();

        // S7: GRU gates — gi units 192 (r2,k4), gh units 192; u in [0,384)
        for (int u = tid; u < 384; u += 256) {
            if (u < 192) {
                int r2 = u / 48, k0i = (u % 48) * 4;
                int r0 = r2 * 2;
                const float4* w4 = (const float4*)(W_ih + k0i);
                float4 bb = *(const float4*)(b_ih + k0i);
                float4 a0 = bb, a1 = bb;
                #pragma unroll 8
                for (int i = 0; i < Hd; i++) {
                    float xa = sx[r0][i], xb = sx[r0 + 1][i];
                    float4 wv = w4[i * 48];
                    a0.x = fmaf(xa, wv.x, a0.x); a0.y = fmaf(xa, wv.y, a0.y);
                    a0.z = fmaf(xa, wv.z, a0.z); a0.w = fmaf(xa, wv.w, a0.w);
                    a1.x = fmaf(xb, wv.x, a1.x); a1.y = fmaf(xb, wv.y, a1.y);
                    a1.z = fmaf(xb, wv.z, a1.z); a1.w = fmaf(xb, wv.w, a1.w);
                }
                #pragma unroll 8
                for (int i = 0; i < Hd; i++) {
                    float xa = s_pz[r0][i], xb = s_pz[r0 + 1][i];
                    float4 wv = w4[(Hd + i) * 48];
                    a0.x = fmaf(xa, wv.x, a0.x); a0.y = fmaf(xa, wv.y, a0.y);
                    a0.z = fmaf(xa, wv.z, a0.z); a0.w = fmaf(xa, wv.w, a0.w);
                    a1.x = fmaf(xb, wv.x, a1.x); a1.y = fmaf(xb, wv.y, a1.y);
                    a1.z = fmaf(xb, wv.z, a1.z); a1.w = fmaf(xb, wv.w, a1.w);
                }
                *(float4*)&s_gi[r0][k0i] = a0;
                *(float4*)&s_gi[r0 + 1][k0i] = a1;
            } else {
                int gu = u - 192;
                int r2 = gu / 48, k0i = (gu % 48) * 4;
                int r0 = r2 * 2;
                const float4* w4 = (const float4*)(W_hh + k0i);
                float4 bb = *(const float4*)(b_hh + k0i);
                float4 a0 = bb, a1 = bb;
                #pragma unroll 8
                for (int i = 0; i < Hd; i++) {
                    float xa = sh[r0][i], xb = sh[r0 + 1][i];
                    float4 wv = w4[i * 48];
                    a0.x = fmaf(xa, wv.x, a0.x); a0.y = fmaf(xa, wv.y, a0.y);
                    a0.z = fmaf(xa, wv.z, a0.z); a0.w = fmaf(xa, wv.w, a0.w);
                    a1.x = fmaf(xb, wv.x, a1.x); a1.y = fmaf(xb, wv.y, a1.y);
                    a1.z = fmaf(xb, wv.z, a1.z); a1.w = fmaf(xb, wv.w, a1.w);
                }
                *(float4*)&s_gh[r0][k0i] = a0;
                *(float4*)&s_gh[r0 + 1][k0i] = a1;
            }
        }
        __syncthreads();

        // S8: h update — 512 elements
        for (int idx = tid; idx < Rr * Hd; idx += 256) {
            int r = idx >> 6, j = idx & 63;
            float ir = s_gi[r][j], iz = s_gi[r][Hd + j], in_ = s_gi[r][2 * Hd + j];
            float hr = s_gh[r][j], hz = s_gh[r][Hd + j], hn  = s_gh[r][2 * Hd + j];
            float rg = sigmoidf(ir + hr);
            float zz = sigmoidf(iz + hz);
            float nn = tanhf(fmaf(rg, hn, in_));
            sh[r][j] = (1.0f - zz) * nn + zz * sh[r][j];
        }
        __syncthreads();
    }

    // reduce per-thread KL: warp w holds row rS == w
    #pragma unroll
    for (int off = 16; off; off >>= 1)
        kl_acc += __shfl_xor_sync(0xFFFFFFFFu, kl_acc, off);
    if ((tid & 31) == 0) s_kld[rS] = kl_acc;
    __syncthreads();

    // ---------- epilogue ----------
    // prior h1
    for (int u = tid; u < NZv * 16 * 4; u += 256) {
        int r2 = u / 80, rem = u % 80;
        int n = rem >> 4, o0 = (rem & 15) * 4;
        int r0 = r2 * 2;
        const float4* w4 = (const float4*)(Wq1 + (size_t)n * Hd * Hd + o0);
        float4 bb = *(const float4*)(bq1 + n * Hd + o0);
        float4 a0 = bb, a1 = bb;
        #pragma unroll 8
        for (int i = 0; i < Hd; i++) {
            float xa = sh[r0][i], xb = sh[r0 + 1][i];
            float4 wv = w4[i * 16];
            a0.x = fmaf(xa, wv.x, a0.x); a0.y = fmaf(xa, wv.y, a0.y);
            a0.z = fmaf(xa, wv.z, a0.z); a0.w = fmaf(xa, wv.w, a0.w);
            a1.x = fmaf(xb, wv.x, a1.x); a1.y = fmaf(xb, wv.y, a1.y);
            a1.z = fmaf(xb, wv.z, a1.z); a1.w = fmaf(xb, wv.w, a1.w);
        }
        float* d0 = &s_h1[r0][n][o0];
        float* d1 = &s_h1[r0 + 1][n][o0];
        d0[0] = fmaxf(a0.x, 0.f); d0[1] = fmaxf(a0.y, 0.f); d0[2] = fmaxf(a0.z, 0.f); d0[3] = fmaxf(a0.w, 0.f);
        d1[0] = fmaxf(a1.x, 0.f); d1[1] = fmaxf(a1.y, 0.f); d1[2] = fmaxf(a1.z, 0.f); d1[3] = fmaxf(a1.w, 0.f);
    }
    __syncthreads();
    // m_prior -> z (t = Tn)
    {
        float m0 = 0.f, m1 = 0.f;
        for (int n = 0; n < NZv; n++) {
            float t0a = bq2[n * Hd + z0], t1a = bq2[n * Hd + z0 + 1];
            const float2* w2 = (const float2*)(Wq2 + (size_t)n * Hd * Hd + z0);
            #pragma unroll 8
            for (int o = 0; o < Hd; o++) {
                float hv = s_h1[rS][n][o];
                float2 wv = w2[o * 32];
                t0a = fmaf(hv, wv.x, t0a);
                t1a = fmaf(hv, wv.y, t1a);
            }
            float g = gprior[n];
            m0 = fmaf(g, t0a, m0);
            m1 = fmaf(g, t1a, m1);
        }
        const float* ep = g_eps + ((size_t)Tn * Bn + row0 + rS) * Hd + z0;
        s_z[rS][z0]     = fmaf(softplusf(m0), ep[0], fmaxf(m0, 0.f));
        s_z[rS][z0 + 1] = fmaf(softplusf(m1), ep[1], fmaxf(m1, 0.f));
    }
    __syncthreads();
    // phi_z
    {
        float a0 = b_z[z0], a1 = b_z[z0 + 1];
        const float2* w2 = (const float2*)(W_z + z0);
        #pragma unroll 8
        for (int i = 0; i < Hd; i++) {
            float xv = s_z[rS][i];
            float2 wv = w2[i * 32];
            a0 = fmaf(xv, wv.x, a0);
            a1 = fmaf(xv, wv.y, a1);
        }
        s_pz[rS][z0] = fmaxf(a0, 0.f);
        s_pz[rS][z0 + 1] = fmaxf(a1, 0.f);
    }
    __syncthreads();
    // dec = relu([phi_z, h] @ W_dec + b_dec) -> sx
    {
        float a0 = b_dec[z0], a1 = b_dec[z0 + 1];
        const float2* w2 = (const float2*)(W_dec + z0);
        #pragma unroll 8
        for (int i = 0; i < Hd; i++) {
            float xv = s_pz[rS][i];
            float2 wv = w2[i * 32];
            a0 = fmaf(xv, wv.x, a0);
            a1 = fmaf(xv, wv.y, a1);
        }
        #pragma unroll 8
        for (int i = 0; i < Hd; i++) {
            float xv = sh[rS][i];
            float2 wv = w2[(Hd + i) * 32];
            a0 = fmaf(xv, wv.x, a0);
            a1 = fmaf(xv, wv.y, a1);
        }
        sx[rS][z0] = fmaxf(a0, 0.f);
        sx[rS][z0 + 1] = fmaxf(a1, 0.f);
    }
    __syncthreads();
    // logits = dec @ W_a + b_a  (160 outputs)
    if (tid < Rr * ACTD) {
        int r = tid / ACTD, a = tid % ACTD;
        float acc = b_a[a];
        #pragma unroll 8
        for (int j = 0; j < Hd; j++) acc = fmaf(sx[r][j], W_a[j * ACTD + a], acc);
        s_gi[r][a] = acc;
        out[(size_t)(row0 + r) * ACTD + a] = acc;
    }
    __syncthreads();
    // phi_logits = relu(logits @ W_act + b_act) -> s_mp
    {
        float a0 = b_act[z0], a1 = b_act[z0 + 1];
        const float2* w2 = (const float2*)(W_act + z0);
        #pragma unroll
        for (int a = 0; a < ACTD; a++) {
            float xv = s_gi[rS][a];
            float2 wv = w2[a * 32];
            a0 = fmaf(xv, wv.x, a0);
            a1 = fmaf(xv, wv.y, a1);
        }
        s_mp[rS][z0] = fmaxf(a0, 0.f);
        s_mp[rS][z0 + 1] = fmaxf(a1, 0.f);
    }
    __syncthreads();
    if (tid < Rr) {
        int r = tid;
        float acc = b_durd[0];
        #pragma unroll 8
        for (int j = 0; j < Hd; j++) acc = fmaf(s_mp[r][j], W_durd[j], acc);
        #pragma unroll 8
        for (int j = 0; j < Hd; j++) acc = fmaf(sx[r][j],  W_durd[Hd + j], acc);
        out[(size_t)Bn * ACTD + row0 + r] = acc;
        out[(size_t)Bn * ACTD + Bn + row0 + r] = softplusf(acc);
        g_kld[row0 + r] = s_kld[r];
    }
}

// ---------------- kernel 4: kld mean ----------------
__global__ void __launch_bounds__(256) kld_reduce_kernel(float* __restrict__ out) {
    __shared__ float s[256];
    int tid = threadIdx.x;
    s[tid] = g_kld[tid] + g_kld[tid + 256] + g_kld[tid + 512] + g_kld[tid + 768];
    __syncthreads();
    for (int st = 128; st > 0; st >>= 1) {
        if (tid < st) s[tid] += s[tid + st];
        __syncthreads();
    }
    if (tid == 0) out[(size_t)Bn * ACTD + 2 * Bn] = s[0] * (1.0f / Bn);
}

// ---------------- launch ----------------
extern "C" void kernel_launch(void* const* d_in, const int* in_sizes, int n_in,
                              void* d_out, int out_size) {
    const int*   acts   = (const int*)  d_in[0];
    const float* durs   = (const float*)d_in[1];
    const float* W_act  = (const float*)d_in[2];
    const float* b_act  = (const float*)d_in[3];
    const float* W_dur  = (const float*)d_in[4];
    const float* b_dur  = (const float*)d_in[5];
    const float* W_x    = (const float*)d_in[6];
    const float* b_x    = (const float*)d_in[7];
    const float* W_z    = (const float*)d_in[8];
    const float* b_z    = (const float*)d_in[9];
    const float* Wp1    = (const float*)d_in[10];
    const float* bp1    = (const float*)d_in[11];
    const float* Wp2    = (const float*)d_in[12];
    const float* bp2    = (const float*)d_in[13];
    const float* Wq1    = (const float*)d_in[14];
    const float* bq1    = (const float*)d_in[15];
    const float* Wq2    = (const float*)d_in[16];
    const float* bq2    = (const float*)d_in[17];
    const float* W_dec  = (const float*)d_in[18];
    const float* b_dec  = (const float*)d_in[19];
    const float* W_a    = (const float*)d_in[20];
    const float* b_a    = (const float*)d_in[21];
    const float* W_durd = (const float*)d_in[22];
    const float* b_durd = (const float*)d_in[23];
    const float* W_ih   = (const float*)d_in[24];
    const float* W_hh   = (const float*)d_in[25];
    const float* b_ih   = (const float*)d_in[26];
    const float* b_hh   = (const float*)d_in[27];
    const float* gpost  = (const float*)d_in[28];
    const float* gprior = (const float*)d_in[29];
    float* out = (float*)d_out;

    eps_kernel<<<((Tn + 1) * Bn * Hd) / 256, 256>>>();
    embed_kernel<<<Bn * Tn / 8, 128>>>(acts, durs, W_act, b_act, W_dur, b_dur, W_x, b_x);
    scan_kernel<<<Bn / Rr, 256>>>(
        W_act, b_act, W_z, b_z, Wp1, bp1, Wp2, bp2, Wq1, bq1, Wq2, bq2,
        W_dec, b_dec, W_a, b_a, W_durd, b_durd, W_ih, W_hh, b_ih, b_hh,
        gpost, gprior, out);
    kld_reduce_kernel<<<1, 256>>>(out);
}

// round 5
// speedup vs baseline: 1.5133x; 1.1769x over previous
#include <cuda_runtime.h>

#define Bn 1024
#define Tn 128
#define Hd 64
#define NZv 5
#define ACTD 20
#define Rr 8
#define SCAN_BLOCKS 128
#define EPS_T_BLOCKS 256     // 256 blocks x 256 threads = 65536 outputs per timestep

typedef unsigned long long ull;

// ---------------- device scratch (static allocation only) ----------------
__device__ float g_eps[(size_t)(Tn + 1) * Bn * Hd];     // (T+1,B,H)
__device__ float g_kld[Bn];
__device__ int   g_done[Tn + 1];
__device__ unsigned g_one = 1;   // runtime-opaque 1: forces adds onto IMAD (fma pipe)

// ---------------- f32x2 packed helpers ----------------
__device__ __forceinline__ ull pk2(float lo, float hi) {
    ull r; asm("mov.b64 %0, {%1, %2};" : "=l"(r) : "f"(lo), "f"(hi)); return r;
}
__device__ __forceinline__ void unpk2(ull v, float& lo, float& hi) {
    asm("mov.b64 {%0, %1}, %2;" : "=f"(lo), "=f"(hi) : "l"(v));
}
__device__ __forceinline__ ull pki2(unsigned lo, unsigned hi) {
    ull r; asm("mov.b64 %0, {%1, %2};" : "=l"(r) : "r"(lo), "r"(hi)); return r;
}
__device__ __forceinline__ ull fma2(ull a, ull b, ull c) {
    ull d; asm("fma.rn.f32x2 %0, %1, %2, %3;" : "=l"(d) : "l"(a), "l"(b), "l"(c)); return d;
}
__device__ __forceinline__ ull mul2(ull a, ull b) {
    ull d; asm("mul.rn.f32x2 %0, %1, %2;" : "=l"(d) : "l"(a), "l"(b)); return d;
}
__device__ __forceinline__ ull add2(ull a, ull b) {
    ull d; asm("add.rn.f32x2 %0, %1, %2;" : "=l"(d) : "l"(a), "l"(b)); return d;
}
__device__ __forceinline__ ull dup2(float x) { return pk2(x, x); }

// ---------------- math helpers ----------------
__device__ __forceinline__ float softplusf(float x) {
    return fmaxf(x, 0.0f) + log1pf(expf(-fabsf(x)));
}
__device__ __forceinline__ float sigmoidf(float x) {
    return 1.0f / (1.0f + expf(-x));
}

// add via IMAD so it issues on the fma pipe (alu pipe is the bottleneck)
__device__ __forceinline__ unsigned imadd(unsigned a, unsigned b, unsigned one) {
    unsigned d;
    asm("mad.lo.u32 %0, %1, %2, %3;" : "=r"(d) : "r"(a), "r"(one), "r"(b));
    return d;
}

// rare tail of Giles erfinv (w >= 5), scalar; identical math to R4's else-branch
__device__ __forceinline__ float tail_norm(float w, float u) {
    w = sqrtf(w) - 3.0f;
    float p = -0.000200214257f;
    p = fmaf(p, w, 0.000100950558f);
    p = fmaf(p, w, 0.00134934322f);
    p = fmaf(p, w, -0.00367342844f);
    p = fmaf(p, w, 0.00573950773f);
    p = fmaf(p, w, -0.0076224613f);
    p = fmaf(p, w, 0.00943887047f);
    p = fmaf(p, w, 1.00167406f);
    p = fmaf(p, w, 2.83297682f);
    return 1.41421356f * (p * u);
}

// general threefry (prologue key fold only)
__device__ __forceinline__ uint2 threefry2x32(unsigned k0, unsigned k1,
                                              unsigned x0, unsigned x1) {
    unsigned ks2 = k0 ^ k1 ^ 0x1BD11BDAu;
#define TF_RND(r) { x0 += x1; x1 = __funnelshift_l(x1, x1, r); x1 ^= x0; }
    x0 += k0; x1 += k1;
    TF_RND(13) TF_RND(15) TF_RND(26) TF_RND(6)
    x0 += k1;  x1 += ks2 + 1u;
    TF_RND(17) TF_RND(29) TF_RND(16) TF_RND(24)
    x0 += ks2; x1 += k0 + 2u;
    TF_RND(13) TF_RND(15) TF_RND(26) TF_RND(6)
    x0 += k0;  x1 += k1 + 3u;
    TF_RND(17) TF_RND(29) TF_RND(16) TF_RND(24)
    x0 += k1;  x1 += ks2 + 4u;
    TF_RND(13) TF_RND(15) TF_RND(26) TF_RND(6)
    x0 += ks2; x1 += k0 + 5u;
#undef TF_RND
    uint2 r; r.x = x0; r.y = x1; return r;
}

// specialized hot path: counter word0 == 0, adds on the fma pipe, returns y0^y1
__device__ __forceinline__ unsigned tf_xor(
    unsigned k0, unsigned k1, unsigned ks2,
    unsigned c1, unsigned c2, unsigned c3, unsigned c4, unsigned c5,
    unsigned e, unsigned one)
{
    unsigned x0 = k0;
    unsigned x1 = imadd(e, k1, one);
#define TF_RND(r) { x0 = imadd(x1, x0, one); x1 = __funnelshift_l(x1, x1, r); x1 ^= x0; }
    TF_RND(13) TF_RND(15) TF_RND(26) TF_RND(6)
    x0 = imadd(k1, x0, one);  x1 = imadd(c1, x1, one);
    TF_RND(17) TF_RND(29) TF_RND(16) TF_RND(24)
    x0 = imadd(ks2, x0, one); x1 = imadd(c2, x1, one);
    TF_RND(13) TF_RND(15) TF_RND(26) TF_RND(6)
    x0 = imadd(k0, x0, one);  x1 = imadd(c3, x1, one);
    TF_RND(17) TF_RND(29) TF_RND(16) TF_RND(24)
    x0 = imadd(k1, x0, one);  x1 = imadd(c4, x1, one);
    TF_RND(13) TF_RND(15) TF_RND(26) TF_RND(6)
    x0 = imadd(ks2, x0, one); x1 = imadd(c5, x1, one);
#undef TF_RND
    return x0 ^ x1;
}

// ============================================================================
// EPS role: one thread = one (t, b, z) output, 1000 samples, f32x2 float path
// ============================================================================
__device__ __noinline__ void eps_role(int eb) {
    const int tid = threadIdx.x;
    const int t = eb >> 8;                   // 256 blocks per timestep
    const unsigned bz = (unsigned)((eb & 255) * 256 + tid);
    const int gid = t * (Bn * Hd) + (int)bz;

    const unsigned one = g_one;
    uint2 kk = threefry2x32(0u, 42u, 0u, (unsigned)t);   // fold_in(key(42), t)
    const unsigned k0 = kk.x, k1 = kk.y;
    const unsigned ks2 = k0 ^ k1 ^ 0x1BD11BDAu;
    const unsigned c1 = ks2 + 1u, c2 = k0 + 2u, c3 = k1 + 3u,
                   c4 = ks2 + 4u, c5 = k0 + 5u;

    // packed constants (loop-invariant registers)
    const ull NEGONE2 = dup2(-1.0f);
    const ull TWO2    = dup2(2.0f);
    const ull NEGP2   = dup2(-0.99999994f);
    const ull ONE2    = dup2(1.0f);
    const ull M2P52   = dup2(-2.5f);
    const ull SQ2     = dup2(1.41421356f);
    const ull P0 = dup2(2.81022636e-08f);
    const ull P1 = dup2(3.43273939e-07f);
    const ull P2 = dup2(-3.5233877e-06f);
    const ull P3 = dup2(-4.39150654e-06f);
    const ull P4 = dup2(0.00021858087f);
    const ull P5 = dup2(-0.00125372503f);
    const ull P6 = dup2(-0.00417768164f);
    const ull P7 = dup2(0.246640727f);
    const ull P8 = dup2(1.50140941f);

    ull sumA = 0ull, sumB = 0ull;            // (0.0f, 0.0f) packed
    unsigned e0 = bz, e1 = bz + 65536u, e2 = bz + 131072u, e3 = bz + 196608u;
    const unsigned step = 262144u;

    #pragma unroll 2
    for (int s = 0; s < 250; s++) {
        unsigned b0 = tf_xor(k0, k1, ks2, c1, c2, c3, c4, c5, e0, one);
        unsigned b1 = tf_xor(k0, k1, ks2, c1, c2, c3, c4, c5, e1, one);
        unsigned b2 = tf_xor(k0, k1, ks2, c1, c2, c3, c4, c5, e2, one);
        unsigned b3 = tf_xor(k0, k1, ks2, c1, c2, c3, c4, c5, e3, one);

        #pragma unroll
        for (int pr = 0; pr < 2; pr++) {
            unsigned ma = ((pr ? b2 : b0) >> 9) | 0x3F800000u;
            unsigned mb = ((pr ? b3 : b1) >> 9) | 0x3F800000u;
            ull g  = pki2(ma, mb);             // in [1,2)
            ull f  = add2(g, NEGONE2);         // exact: g-1
            ull u  = fma2(f, TWO2, NEGP2);     // 2f - 0.99999994 (== ref, per lane)
            ull nu = mul2(u, NEGONE2);
            ull t1 = fma2(nu, u, ONE2);        // 1 - u^2 (fmaf(-u,u,1) per lane)
            float t1a, t1b; unpk2(t1, t1a, t1b);
            float wa = __log2f(t1a) * -0.69314718f;   // == -__logf(t1a)
            float wb = __log2f(t1b) * -0.69314718f;
            ull wk = add2(pk2(wa, wb), M2P52);
            ull p = fma2(P0, wk, P1);
            p = fma2(p, wk, P2);
            p = fma2(p, wk, P3);
            p = fma2(p, wk, P4);
            p = fma2(p, wk, P5);
            p = fma2(p, wk, P6);
            p = fma2(p, wk, P7);
            p = fma2(p, wk, P8);
            ull r = mul2(mul2(p, u), SQ2);
            if (!(wa < 5.0f) || !(wb < 5.0f)) {        // rare tail fixup
                float ua, ub, ra, rb;
                unpk2(u, ua, ub); unpk2(r, ra, rb);
                if (!(wa < 5.0f)) ra = tail_norm(wa, ua);
                if (!(wb < 5.0f)) rb = tail_norm(wb, ub);
                r = pk2(ra, rb);
            }
            if (pr == 0) sumA = add2(sumA, r); else sumB = add2(sumB, r);
        }
        e0 = imadd(step, e0, one); e1 = imadd(step, e1, one);
        e2 = imadd(step, e2, one); e3 = imadd(step, e3, one);
    }
    float s0, s1, s2, s3;
    unpk2(sumA, s0, s1); unpk2(sumB, s2, s3);
    g_eps[gid] = ((s0 + s1) + (s2 + s3)) * 0.001f;

    // release this block's 256 outputs
    __threadfence();
    __syncthreads();
    if (tid == 0) atomicAdd(&g_done[t], 1);
}

// ============================================================================
// SCAN role: 8 batch rows per block; embed folded in; waits on g_done[t]
// ============================================================================
__device__ void scan_role(
    const int* __restrict__ acts, const float* __restrict__ durs,
    const float* __restrict__ W_act, const float* __restrict__ b_act,
    const float* __restrict__ W_dur, const float* __restrict__ b_dur,
    const float* __restrict__ W_x,  const float* __restrict__ b_x,
    const float* __restrict__ W_z,  const float* __restrict__ b_z,
    const float* __restrict__ Wp1,  const float* __restrict__ bp1,
    const float* __restrict__ Wp2,  const float* __restrict__ bp2,
    const float* __restrict__ Wq1,  const float* __restrict__ bq1,
    const float* __restrict__ Wq2,  const float* __restrict__ bq2,
    const float* __restrict__ W_dec,const float* __restrict__ b_dec,
    const float* __restrict__ W_a,  const float* __restrict__ b_a,
    const float* __restrict__ W_durd,const float* __restrict__ b_durd,
    const float* __restrict__ W_ih, const float* __restrict__ W_hh,
    const float* __restrict__ b_ih, const float* __restrict__ b_hh,
    const float* __restrict__ gpost,const float* __restrict__ gprior,
    float* __restrict__ out)
{
    __shared__ float sh[Rr][Hd];
    __shared__ float sx[Rr][Hd];            // phi_x; reused as dec in epilogue
    __shared__ float s_inp[Rr][2 * Hd];     // embed input
    __shared__ int   s_act[Rr];
    __shared__ float s_dur[Rr];
    __shared__ float s_h1[Rr][NZv][Hd];
    __shared__ float s_mp[Rr][Hd];
    __shared__ float s_mq[Rr][Hd];
    __shared__ float s_z[Rr][Hd];
    __shared__ float s_pz[Rr][Hd];
    __shared__ float s_gi[Rr][3 * Hd];
    __shared__ float s_gh[Rr][3 * Hd];
    __shared__ float s_kld[Rr];

    const int tid = threadIdx.x;
    const int row0 = blockIdx.x * Rr;
    float kl_acc = 0.0f;

    if (tid < Rr * Hd / 4)
        ((float4*)sh)[tid] = make_float4(0.f, 0.f, 0.f, 0.f);
    __syncthreads();

    const int rS = tid >> 5;
    const int z0 = (tid & 31) * 2;

    for (int t = 0; t < Tn; t++) {
        // S0: embed (one_hot @ W_act is a row gather) -> phi_x in sx
        if (tid < Rr) {
            s_act[tid] = acts[(row0 + tid) * Tn + t];
            s_dur[tid] = durs[(row0 + tid) * Tn + t];
        }
        __syncthreads();
        for (int idx = tid; idx < Rr * 2 * Hd; idx += 256) {
            int r = idx >> 7, c = idx & 127;
            float v;
            if (c < Hd) v = W_act[s_act[r] * Hd + c] + b_act[c];
            else        v = fmaf(s_dur[r], W_dur[c - Hd], b_dur[c - Hd]);
            s_inp[r][c] = fmaxf(v, 0.f);
        }
        __syncthreads();
        {
            float a0 = b_x[z0], a1 = b_x[z0 + 1];
            const float2* w2 = (const float2*)(W_x + z0);
            #pragma unroll 8
            for (int i = 0; i < 2 * Hd; i++) {
                float xv = s_inp[rS][i];
                float2 wv = w2[i * 32];
                a0 = fmaf(xv, wv.x, a0);
                a1 = fmaf(xv, wv.y, a1);
            }
            sx[rS][z0] = fmaxf(a0, 0.f);
            sx[rS][z0 + 1] = fmaxf(a1, 0.f);
        }
        __syncthreads();

        // S1: h1 = relu([phi_x,h] @ Wp1[n] + bp1)
        for (int u = tid; u < NZv * 16 * 4; u += 256) {
            int r2 = u / 80, rem = u % 80;
            int n = rem >> 4, o0 = (rem & 15) * 4;
            int r0 = r2 * 2;
            const float4* w4 = (const float4*)(Wp1 + (size_t)n * 128 * Hd + o0);
            float4 bb = *(const float4*)(bp1 + n * Hd + o0);
            float4 a0 = bb, a1 = bb;
            #pragma unroll 8
            for (int i = 0; i < Hd; i++) {
                float xa = sx[r0][i], xb = sx[r0 + 1][i];
                float4 wv = w4[i * 16];
                a0.x = fmaf(xa, wv.x, a0.x); a0.y = fmaf(xa, wv.y, a0.y);
                a0.z = fmaf(xa, wv.z, a0.z); a0.w = fmaf(xa, wv.w, a0.w);
                a1.x = fmaf(xb, wv.x, a1.x); a1.y = fmaf(xb, wv.y, a1.y);
                a1.z = fmaf(xb, wv.z, a1.z); a1.w = fmaf(xb, wv.w, a1.w);
            }
            #pragma unroll 8
            for (int i = 0; i < Hd; i++) {
                float xa = sh[r0][i], xb = sh[r0 + 1][i];
                float4 wv = w4[(Hd + i) * 16];
                a0.x = fmaf(xa, wv.x, a0.x); a0.y = fmaf(xa, wv.y, a0.y);
                a0.z = fmaf(xa, wv.z, a0.z); a0.w = fmaf(xa, wv.w, a0.w);
                a1.x = fmaf(xb, wv.x, a1.x); a1.y = fmaf(xb, wv.y, a1.y);
                a1.z = fmaf(xb, wv.z, a1.z); a1.w = fmaf(xb, wv.w, a1.w);
            }
            float* d0 = &s_h1[r0][n][o0];
            float* d1 = &s_h1[r0 + 1][n][o0];
            d0[0] = fmaxf(a0.x, 0.f); d0[1] = fmaxf(a0.y, 0.f); d0[2] = fmaxf(a0.z, 0.f); d0[3] = fmaxf(a0.w, 0.f);
            d1[0] = fmaxf(a1.x, 0.f); d1[1] = fmaxf(a1.y, 0.f); d1[2] = fmaxf(a1.z, 0.f); d1[3] = fmaxf(a1.w, 0.f);
        }
        __syncthreads();

        // S2: m_post
        {
            float m0 = 0.f, m1 = 0.f;
            for (int n = 0; n < NZv; n++) {
                float t0a = bp2[n * Hd + z0], t1a = bp2[n * Hd + z0 + 1];
                const float2* w2 = (const float2*)(Wp2 + (size_t)n * Hd * Hd + z0);
                #pragma unroll 8
                for (int o = 0; o < Hd; o++) {
                    float hv = s_h1[rS][n][o];
                    float2 wv = w2[o * 32];
                    t0a = fmaf(hv, wv.x, t0a);
                    t1a = fmaf(hv, wv.y, t1a);
                }
                float g = gpost[n];
                m0 = fmaf(g, t0a, m0);
                m1 = fmaf(g, t1a, m1);
            }
            s_mp[rS][z0] = m0; s_mp[rS][z0 + 1] = m1;
        }
        __syncthreads();

        // S3: prior h1 = relu(h @ Wq1[n] + bq1)
        for (int u = tid; u < NZv * 16 * 4; u += 256) {
            int r2 = u / 80, rem = u % 80;
            int n = rem >> 4, o0 = (rem & 15) * 4;
            int r0 = r2 * 2;
            const float4* w4 = (const float4*)(Wq1 + (size_t)n * Hd * Hd + o0);
            float4 bb = *(const float4*)(bq1 + n * Hd + o0);
            float4 a0 = bb, a1 = bb;
            #pragma unroll 8
            for (int i = 0; i < Hd; i++) {
                float xa = sh[r0][i], xb = sh[r0 + 1][i];
                float4 wv = w4[i * 16];
                a0.x = fmaf(xa, wv.x, a0.x); a0.y = fmaf(xa, wv.y, a0.y);
                a0.z = fmaf(xa, wv.z, a0.z); a0.w = fmaf(xa, wv.w, a0.w);
                a1.x = fmaf(xb, wv.x, a1.x); a1.y = fmaf(xb, wv.y, a1.y);
                a1.z = fmaf(xb, wv.z, a1.z); a1.w = fmaf(xb, wv.w, a1.w);
            }
            float* d0 = &s_h1[r0][n][o0];
            float* d1 = &s_h1[r0 + 1][n][o0];
            d0[0] = fmaxf(a0.x, 0.f); d0[1] = fmaxf(a0.y, 0.f); d0[2] = fmaxf(a0.z, 0.f); d0[3] = fmaxf(a0.w, 0.f);
            d1[0] = fmaxf(a1.x, 0.f); d1[1] = fmaxf(a1.y, 0.f); d1[2] = fmaxf(a1.z, 0.f); d1[3] = fmaxf(a1.w, 0.f);
        }
        __syncthreads();

        // S4: m_prior
        {
            float m0 = 0.f, m1 = 0.f;
            for (int n = 0; n < NZv; n++) {
                float t0a = bq2[n * Hd + z0], t1a = bq2[n * Hd + z0 + 1];
                const float2* w2 = (const float2*)(Wq2 + (size_t)n * Hd * Hd + z0);
                #pragma unroll 8
                for (int o = 0; o < Hd; o++) {
                    float hv = s_h1[rS][n][o];
                    float2 wv = w2[o * 32];
                    t0a = fmaf(hv, wv.x, t0a);
                    t1a = fmaf(hv, wv.y, t1a);
                }
                float g = gprior[n];
                m0 = fmaf(g, t0a, m0);
                m1 = fmaf(g, t1a, m1);
            }
            s_mq[rS][z0] = m0; s_mq[rS][z0 + 1] = m1;
        }
        __syncthreads();

        // wait for eps slice t (produced by eps-role blocks)
        if (tid == 0) {
            while (atomicAdd(&g_done[t], 0) < EPS_T_BLOCKS) __nanosleep(200);
            __threadfence();
        }
        __syncthreads();

        // S5: KL + z
        {
            const float* ep = g_eps + ((size_t)t * Bn + row0 + rS) * Hd + z0;
            #pragma unroll
            for (int q = 0; q < 2; q++) {
                float mp = s_mp[rS][z0 + q], mq = s_mq[rS][z0 + q];
                float pm = fmaxf(mp, 0.0f), qm = fmaxf(mq, 0.0f);
                float ps = softplusf(mp),   qs = softplusf(mq);
                float d = pm - qm;
                kl_acc += logf(qs / ps) + (ps * ps + d * d) / (2.0f * qs * qs) - 0.5f;
                s_z[rS][z0 + q] = fmaf(ps, ep[q], pm);
            }
        }
        __syncthreads();

        // S6: phi_z
        {
            float a0 = b_z[z0], a1 = b_z[z0 + 1];
            const float2* w2 = (const float2*)(W_z + z0);
            #pragma unroll 8
            for (int i = 0; i < Hd; i++) {
                float xv = s_z[rS][i];
                float2 wv = w2[i * 32];
                a0 = fmaf(xv, wv.x, a0);
                a1 = fmaf(xv, wv.y, a1);
            }
            s_pz[rS][z0] = fmaxf(a0, 0.f);
            s_pz[rS][z0 + 1] = fmaxf(a1, 0.f);
        }
        __syncthreads();

        // S7: GRU gates
        for (int u = tid; u < 384; u += 256) {
            if (u < 192) {
                int r2 = u / 48, k0i = (u % 48) * 4;
                int r0 = r2 * 2;
                const float4* w4 = (const float4*)(W_ih + k0i);
                float4 bb = *(const float4*)(b_ih + k0i);
                float4 a0 = bb, a1 = bb;
                #pragma unroll 8
                for (int i = 0; i < Hd; i++) {
                    float xa = sx[r0][i], xb = sx[r0 + 1][i];
                    float4 wv = w4[i * 48];
                    a0.x = fmaf(xa, wv.x, a0.x); a0.y = fmaf(xa, wv.y, a0.y);
                    a0.z = fmaf(xa, wv.z, a0.z); a0.w = fmaf(xa, wv.w, a0.w);
                    a1.x = fmaf(xb, wv.x, a1.x); a1.y = fmaf(xb, wv.y, a1.y);
                    a1.z = fmaf(xb, wv.z, a1.z); a1.w = fmaf(xb, wv.w, a1.w);
                }
                #pragma unroll 8
                for (int i = 0; i < Hd; i++) {
                    float xa = s_pz[r0][i], xb = s_pz[r0 + 1][i];
                    float4 wv = w4[(Hd + i) * 48];
                    a0.x = fmaf(xa, wv.x, a0.x); a0.y = fmaf(xa, wv.y, a0.y);
                    a0.z = fmaf(xa, wv.z, a0.z); a0.w = fmaf(xa, wv.w, a0.w);
                    a1.x = fmaf(xb, wv.x, a1.x); a1.y = fmaf(xb, wv.y, a1.y);
                    a1.z = fmaf(xb, wv.z, a1.z); a1.w = fmaf(xb, wv.w, a1.w);
                }
                *(float4*)&s_gi[r0][k0i] = a0;
                *(float4*)&s_gi[r0 + 1][k0i] = a1;
            } else {
                int gu = u - 192;
                int r2 = gu / 48, k0i = (gu % 48) * 4;
                int r0 = r2 * 2;
                const float4* w4 = (const float4*)(W_hh + k0i);
                float4 bb = *(const float4*)(b_hh + k0i);
                float4 a0 = bb, a1 = bb;
                #pragma unroll 8
                for (int i = 0; i < Hd; i++) {
                    float xa = sh[r0][i], xb = sh[r0 + 1][i];
                    float4 wv = w4[i * 48];
                    a0.x = fmaf(xa, wv.x, a0.x); a0.y = fmaf(xa, wv.y, a0.y);
                    a0.z = fmaf(xa, wv.z, a0.z); a0.w = fmaf(xa, wv.w, a0.w);
                    a1.x = fmaf(xb, wv.x, a1.x); a1.y = fmaf(xb, wv.y, a1.y);
                    a1.z = fmaf(xb, wv.z, a1.z); a1.w = fmaf(xb, wv.w, a1.w);
                }
                *(float4*)&s_gh[r0][k0i] = a0;
                *(float4*)&s_gh[r0 + 1][k0i] = a1;
            }
        }
        __syncthreads();

        // S8: h update
        for (int idx = tid; idx < Rr * Hd; idx += 256) {
            int r = idx >> 6, j = idx & 63;
            float ir = s_gi[r][j], iz = s_gi[r][Hd + j], in_ = s_gi[r][2 * Hd + j];
            float hr = s_gh[r][j], hz = s_gh[r][Hd + j], hn  = s_gh[r][2 * Hd + j];
            float rg = sigmoidf(ir + hr);
            float zz = sigmoidf(iz + hz);
            float nn = tanhf(fmaf(rg, hn, in_));
            sh[r][j] = (1.0f - zz) * nn + zz * sh[r][j];
        }
        __syncthreads();
    }

    // reduce per-thread KL
    #pragma unroll
    for (int off = 16; off; off >>= 1)
        kl_acc += __shfl_xor_sync(0xFFFFFFFFu, kl_acc, off);
    if ((tid & 31) == 0) s_kld[rS] = kl_acc;
    __syncthreads();

    // ---------- epilogue ----------
    for (int u = tid; u < NZv * 16 * 4; u += 256) {
        int r2 = u / 80, rem = u % 80;
        int n = rem >> 4, o0 = (rem & 15) * 4;
        int r0 = r2 * 2;
        const float4* w4 = (const float4*)(Wq1 + (size_t)n * Hd * Hd + o0);
        float4 bb = *(const float4*)(bq1 + n * Hd + o0);
        float4 a0 = bb, a1 = bb;
        #pragma unroll 8
        for (int i = 0; i < Hd; i++) {
            float xa = sh[r0][i], xb = sh[r0 + 1][i];
            float4 wv = w4[i * 16];
            a0.x = fmaf(xa, wv.x, a0.x); a0.y = fmaf(xa, wv.y, a0.y);
            a0.z = fmaf(xa, wv.z, a0.z); a0.w = fmaf(xa, wv.w, a0.w);
            a1.x = fmaf(xb, wv.x, a1.x); a1.y = fmaf(xb, wv.y, a1.y);
            a1.z = fmaf(xb, wv.z, a1.z); a1.w = fmaf(xb, wv.w, a1.w);
        }
        float* d0 = &s_h1[r0][n][o0];
        float* d1 = &s_h1[r0 + 1][n][o0];
        d0[0] = fmaxf(a0.x, 0.f); d0[1] = fmaxf(a0.y, 0.f); d0[2] = fmaxf(a0.z, 0.f); d0[3] = fmaxf(a0.w, 0.f);
        d1[0] = fmaxf(a1.x, 0.f); d1[1] = fmaxf(a1.y, 0.f); d1[2] = fmaxf(a1.z, 0.f); d1[3] = fmaxf(a1.w, 0.f);
    }
    // wait for eps slice Tn
    if (tid == 0) {
        while (atomicAdd(&g_done[Tn], 0) < EPS_T_BLOCKS) __nanosleep(200);
        __threadfence();
    }
    __syncthreads();
    {
        float m0 = 0.f, m1 = 0.f;
        for (int n = 0; n < NZv; n++) {
            float t0a = bq2[n * Hd + z0], t1a = bq2[n * Hd + z0 + 1];
            const float2* w2 = (const float2*)(Wq2 + (size_t)n * Hd * Hd + z0);
            #pragma unroll 8
            for (int o = 0; o < Hd; o++) {
                float hv = s_h1[rS][n][o];
                float2 wv = w2[o * 32];
                t0a = fmaf(hv, wv.x, t0a);
                t1a = fmaf(hv, wv.y, t1a);
            }
            float g = gprior[n];
            m0 = fmaf(g, t0a, m0);
            m1 = fmaf(g, t1a, m1);
        }
        const float* ep = g_eps + ((size_t)Tn * Bn + row0 + rS) * Hd + z0;
        s_z[rS][z0]     = fmaf(softplusf(m0), ep[0], fmaxf(m0, 0.f));
        s_z[rS][z0 + 1] = fmaf(softplusf(m1), ep[1], fmaxf(m1, 0.f));
    }
    __syncthreads();
    {
        float a0 = b_z[z0], a1 = b_z[z0 + 1];
        const float2* w2 = (const float2*)(W_z + z0);
        #pragma unroll 8
        for (int i = 0; i < Hd; i++) {
            float xv = s_z[rS][i];
            float2 wv = w2[i * 32];
            a0 = fmaf(xv, wv.x, a0);
            a1 = fmaf(xv, wv.y, a1);
        }
        s_pz[rS][z0] = fmaxf(a0, 0.f);
        s_pz[rS][z0 + 1] = fmaxf(a1, 0.f);
    }
    __syncthreads();
    {
        float a0 = b_dec[z0], a1 = b_dec[z0 + 1];
        const float2* w2 = (const float2*)(W_dec + z0);
        #pragma unroll 8
        for (int i = 0; i < Hd; i++) {
            float xv = s_pz[rS][i];
            float2 wv = w2[i * 32];
            a0 = fmaf(xv, wv.x, a0);
            a1 = fmaf(xv, wv.y, a1);
        }
        #pragma unroll 8
        for (int i = 0; i < Hd; i++) {
            float xv = sh[rS][i];
            float2 wv = w2[(Hd + i) * 32];
            a0 = fmaf(xv, wv.x, a0);
            a1 = fmaf(xv, wv.y, a1);
        }
        sx[rS][z0] = fmaxf(a0, 0.f);
        sx[rS][z0 + 1] = fmaxf(a1, 0.f);
    }
    __syncthreads();
    if (tid < Rr * ACTD) {
        int r = tid / ACTD, a = tid % ACTD;
        float acc = b_a[a];
        #pragma unroll 8
        for (int j = 0; j < Hd; j++) acc = fmaf(sx[r][j], W_a[j * ACTD + a], acc);
        s_gi[r][a] = acc;
        out[(size_t)(row0 + r) * ACTD + a] = acc;
    }
    __syncthreads();
    {
        float a0 = b_act[z0], a1 = b_act[z0 + 1];
        const float2* w2 = (const float2*)(W_act + z0);
        #pragma unroll
        for (int a = 0; a < ACTD; a++) {
            float xv = s_gi[rS][a];
            float2 wv = w2[a * 32];
            a0 = fmaf(xv, wv.x, a0);
            a1 = fmaf(xv, wv.y, a1);
        }
        s_mp[rS][z0] = fmaxf(a0, 0.f);
        s_mp[rS][z0 + 1] = fmaxf(a1, 0.f);
    }
    __syncthreads();
    if (tid < Rr) {
        int r = tid;
        float acc = b_durd[0];
        #pragma unroll 8
        for (int j = 0; j < Hd; j++) acc = fmaf(s_mp[r][j], W_durd[j], acc);
        #pragma unroll 8
        for (int j = 0; j < Hd; j++) acc = fmaf(sx[r][j],  W_durd[Hd + j], acc);
        out[(size_t)Bn * ACTD + row0 + r] = acc;
        out[(size_t)Bn * ACTD + Bn + row0 + r] = softplusf(acc);
        g_kld[row0 + r] = s_kld[r];
    }
}

// ============================================================================
// fused kernel: blocks [0,128) = scan, blocks [128, 128+129*256) = eps
// ============================================================================
__global__ void __launch_bounds__(256) fused_kernel(
    const int* __restrict__ acts, const float* __restrict__ durs,
    const float* __restrict__ W_act, const float* __restrict__ b_act,
    const float* __restrict__ W_dur, const float* __restrict__ b_dur,
    const float* __restrict__ W_x,  const float* __restrict__ b_x,
    const float* __restrict__ W_z,  const float* __restrict__ b_z,
    const float* __restrict__ Wp1,  const float* __restrict__ bp1,
    const float* __restrict__ Wp2,  const float* __restrict__ bp2,
    const float* __restrict__ Wq1,  const float* __restrict__ bq1,
    const float* __restrict__ Wq2,  const float* __restrict__ bq2,
    const float* __restrict__ W_dec,const float* __restrict__ b_dec,
    const float* __restrict__ W_a,  const float* __restrict__ b_a,
    const float* __restrict__ W_durd,const float* __restrict__ b_durd,
    const float* __restrict__ W_ih, const float* __restrict__ W_hh,
    const float* __restrict__ b_ih, const float* __restrict__ b_hh,
    const float* __restrict__ gpost,const float* __restrict__ gprior,
    float* __restrict__ out)
{
    if (blockIdx.x >= SCAN_BLOCKS) {
        eps_role(blockIdx.x - SCAN_BLOCKS);
    } else {
        scan_role(acts, durs, W_act, b_act, W_dur, b_dur, W_x, b_x, W_z, b_z,
                  Wp1, bp1, Wp2, bp2, Wq1, bq1, Wq2, bq2, W_dec, b_dec,
                  W_a, b_a, W_durd, b_durd, W_ih, W_hh, b_ih, b_hh,
                  gpost, gprior, out);
    }
}

// ---------------- init: reset handshake counters each run ----------------
__global__ void init_kernel() {
    int i = threadIdx.x;
    if (i <= Tn) g_done[i] = 0;
}

// ---------------- kld mean ----------------
__global__ void __launch_bounds__(256) kld_reduce_kernel(float* __restrict__ out) {
    __shared__ float s[256];
    int tid = threadIdx.x;
    s[tid] = g_kld[tid] + g_kld[tid + 256] + g_kld[tid + 512] + g_kld[tid + 768];
    __syncthreads();
    for (int st = 128; st > 0; st >>= 1) {
        if (tid < st) s[tid] += s[tid + st];
        __syncthreads();
    }
    if (tid == 0) out[(size_t)Bn * ACTD + 2 * Bn] = s[0] * (1.0f / Bn);
}

// ---------------- launch ----------------
extern "C" void kernel_launch(void* const* d_in, const int* in_sizes, int n_in,
                              void* d_out, int out_size) {
    const int*   acts   = (const int*)  d_in[0];
    const float* durs   = (const float*)d_in[1];
    const float* W_act  = (const float*)d_in[2];
    const float* b_act  = (const float*)d_in[3];
    const float* W_dur  = (const float*)d_in[4];
    const float* b_dur  = (const float*)d_in[5];
    const float* W_x    = (const float*)d_in[6];
    const float* b_x    = (const float*)d_in[7];
    const float* W_z    = (const float*)d_in[8];
    const float* b_z    = (const float*)d_in[9];
    const float* Wp1    = (const float*)d_in[10];
    const float* bp1    = (const float*)d_in[11];
    const float* Wp2    = (const float*)d_in[12];
    const float* bp2    = (const float*)d_in[13];
    const float* Wq1    = (const float*)d_in[14];
    const float* bq1    = (const float*)d_in[15];
    const float* Wq2    = (const float*)d_in[16];
    const float* bq2    = (const float*)d_in[17];
    const float* W_dec  = (const float*)d_in[18];
    const float* b_dec  = (const float*)d_in[19];
    const float* W_a    = (const float*)d_in[20];
    const float* b_a    = (const float*)d_in[21];
    const float* W_durd = (const float*)d_in[22];
    const float* b_durd = (const float*)d_in[23];
    const float* W_ih   = (const float*)d_in[24];
    const float* W_hh   = (const float*)d_in[25];
    const float* b_ih   = (const float*)d_in[26];
    const float* b_hh   = (const float*)d_in[27];
    const float* gpost  = (const float*)d_in[28];
    const float* gprior = (const float*)d_in[29];
    float* out = (float*)d_out;

    init_kernel<<<1, 256>>>();
    fused_kernel<<<SCAN_BLOCKS + (Tn + 1) * EPS_T_BLOCKS, 256>>>(
        acts, durs, W_act, b_act, W_dur, b_dur, W_x, b_x, W_z, b_z,
        Wp1, bp1, Wp2, bp2, Wq1, bq1, Wq2, bq2, W_dec, b_dec,
        W_a, b_a, W_durd, b_durd, W_ih, W_hh, b_ih, b_hh,
        gpost, gprior, out);
    kld_reduce_kernel<<<1, 256>>>(out);
}